// round 1
// baseline (speedup 1.0000x reference)
#include <cuda_runtime.h>
#include <cstdint>

// ---------------- problem constants ----------------
#define T_LEN 4096
#define D_DIM 2048
#define H_N   6
#define DKDIM 256
#define DVDIM 512
#define KD    1536   // H_N*DKDIM
#define VD    3072   // H_N*DVDIM
#define GENW  256
#define KSZ   4

// ---------------- scratch (static device, allocation-free) ----------------
__device__ float g_q[(size_t)T_LEN*KD];
__device__ float g_k[(size_t)T_LEN*KD];
__device__ float g_x[(size_t)T_LEN*VD];      // x = h@Wv, later reused as y (post-rmsnorm)
__device__ float g_v[(size_t)T_LEN*VD];      // conv+silu output
__device__ float g_dyn1[(size_t)T_LEN*GENW];
__device__ float g_dyn[(size_t)T_LEN*4];
__device__ float g_eg[(size_t)T_LEN*H_N];    // exp(g)
__device__ float g_beta[(size_t)T_LEN*H_N];
__device__ float g_gate[(size_t)T_LEN*VD];
__device__ float g_o[(size_t)T_LEN*VD];      // scan output

__device__ __forceinline__ float siluf(float x) { return x / (1.0f + expf(-x)); }

// ---------------- SGEMM: C[M,N] = act(A[M,K] @ B[K,N]), all row-major ----------------
// BM=128 BN=128 BK=16, 256 threads, 8x8 per thread. Requires M%128==0, N%128==0, K%16==0.
template<int ACT>
__global__ __launch_bounds__(256)
void sgemm_kernel(const float* __restrict__ A, const float* __restrict__ B,
                  float* __restrict__ C, int M, int N, int K) {
    __shared__ float As[16][128];   // transposed A tile
    __shared__ float Bs[16][128];

    const int tid  = threadIdx.x;
    const int row0 = blockIdx.y * 128;
    const int col0 = blockIdx.x * 128;

    const int aRow = tid >> 2;          // 0..63
    const int aCol = (tid & 3) << 2;    // 0,4,8,12
    const int bRow = tid >> 5;          // 0..7
    const int bCol = (tid & 31) << 2;   // 0..124

    const int trow = (tid >> 4) * 8;
    const int tcol = (tid & 15) * 8;

    float acc[8][8];
    #pragma unroll
    for (int i = 0; i < 8; i++)
        #pragma unroll
        for (int j = 0; j < 8; j++) acc[i][j] = 0.0f;

    const float* Aptr = A + (size_t)row0 * K;
    const float* Bptr = B + col0;

    for (int k0 = 0; k0 < K; k0 += 16) {
        #pragma unroll
        for (int r = 0; r < 2; ++r) {
            float4 t = *(const float4*)(Aptr + (size_t)(aRow + 64*r) * K + k0 + aCol);
            As[aCol+0][aRow+64*r] = t.x;
            As[aCol+1][aRow+64*r] = t.y;
            As[aCol+2][aRow+64*r] = t.z;
            As[aCol+3][aRow+64*r] = t.w;
        }
        #pragma unroll
        for (int r = 0; r < 2; ++r) {
            *(float4*)(&Bs[bRow + 8*r][bCol]) =
                *(const float4*)(Bptr + (size_t)(k0 + bRow + 8*r) * N + bCol);
        }
        __syncthreads();

        #pragma unroll
        for (int kk = 0; kk < 16; ++kk) {
            float ar[8], br[8];
            *(float4*)(ar)   = *(const float4*)(&As[kk][trow]);
            *(float4*)(ar+4) = *(const float4*)(&As[kk][trow+4]);
            *(float4*)(br)   = *(const float4*)(&Bs[kk][tcol]);
            *(float4*)(br+4) = *(const float4*)(&Bs[kk][tcol+4]);
            #pragma unroll
            for (int i = 0; i < 8; ++i)
                #pragma unroll
                for (int j = 0; j < 8; ++j)
                    acc[i][j] += ar[i] * br[j];
        }
        __syncthreads();
    }

    #pragma unroll
    for (int i = 0; i < 8; ++i) {
        float* crow = C + (size_t)(row0 + trow + i) * N + col0 + tcol;
        #pragma unroll
        for (int j = 0; j < 8; j += 4) {
            float4 r;
            r.x = ACT ? siluf(acc[i][j+0]) : acc[i][j+0];
            r.y = ACT ? siluf(acc[i][j+1]) : acc[i][j+1];
            r.z = ACT ? siluf(acc[i][j+2]) : acc[i][j+2];
            r.w = ACT ? siluf(acc[i][j+3]) : acc[i][j+3];
            *(float4*)(crow + j) = r;
        }
    }
}

// ---------------- dyn = dyn1[T,256] @ gen_w2[256,4] (warp per token) ----------------
__global__ __launch_bounds__(256)
void dyn2_kernel(const float* __restrict__ dyn1, const float* __restrict__ w2,
                 float* __restrict__ dyn) {
    int t    = blockIdx.x * 8 + (threadIdx.x >> 5);
    int lane = threadIdx.x & 31;
    const float* r = dyn1 + (size_t)t * GENW;
    float a0 = 0.f, a1 = 0.f, a2 = 0.f, a3 = 0.f;
    #pragma unroll
    for (int i = 0; i < 8; i++) {
        int d = lane + 32*i;
        float v = r[d];
        const float* w = w2 + d*4;
        a0 += v*w[0]; a1 += v*w[1]; a2 += v*w[2]; a3 += v*w[3];
    }
    #pragma unroll
    for (int off = 16; off; off >>= 1) {
        a0 += __shfl_xor_sync(0xffffffffu, a0, off);
        a1 += __shfl_xor_sync(0xffffffffu, a1, off);
        a2 += __shfl_xor_sync(0xffffffffu, a2, off);
        a3 += __shfl_xor_sync(0xffffffffu, a3, off);
    }
    if (lane == 0) {
        dyn[t*4+0] = a0; dyn[t*4+1] = a1; dyn[t*4+2] = a2; dyn[t*4+3] = a3;
    }
}

// ---------------- beta = sigmoid(h@Wb), eg = exp(-exp(A_log)*softplus(h@Wa+dt_bias)) ----------------
__global__ __launch_bounds__(256)
void betag_kernel(const float* __restrict__ h, const float* __restrict__ Wb,
                  const float* __restrict__ Wa, const float* __restrict__ A_log,
                  const float* __restrict__ dt_bias,
                  float* __restrict__ beta, float* __restrict__ eg) {
    int t = blockIdx.x;
    const float* hr = h + (size_t)t * D_DIM;
    float acc[12];
    #pragma unroll
    for (int j = 0; j < 12; j++) acc[j] = 0.f;
    for (int d = threadIdx.x; d < D_DIM; d += 256) {
        float hv = hr[d];
        const float* wb = Wb + d*6;
        const float* wa = Wa + d*6;
        #pragma unroll
        for (int j = 0; j < 6; j++) {
            acc[j]   += hv * wb[j];
            acc[6+j] += hv * wa[j];
        }
    }
    #pragma unroll
    for (int j = 0; j < 12; j++)
        #pragma unroll
        for (int off = 16; off; off >>= 1)
            acc[j] += __shfl_xor_sync(0xffffffffu, acc[j], off);

    __shared__ float red[8][12];
    int w = threadIdx.x >> 5, lane = threadIdx.x & 31;
    if (lane == 0) {
        #pragma unroll
        for (int j = 0; j < 12; j++) red[w][j] = acc[j];
    }
    __syncthreads();
    if (threadIdx.x < 12) {
        float s = 0.f;
        #pragma unroll
        for (int i = 0; i < 8; i++) s += red[i][threadIdx.x];
        int j = threadIdx.x;
        if (j < 6) {
            beta[t*6 + j] = 1.0f / (1.0f + expf(-s));
        } else {
            int hh = j - 6;
            float xx = s + dt_bias[hh];
            float sp = (xx > 20.0f) ? xx : log1pf(expf(xx));
            float g  = -expf(A_log[hh]) * sp;
            eg[t*6 + hh] = expf(g);
        }
    }
}

// ---------------- dynamic short conv + silu ----------------
__global__ __launch_bounds__(256)
void conv_silu_kernel(const float* __restrict__ x, const float* __restrict__ dyn,
                      const float* __restrict__ cw, float* __restrict__ v) {
    int idx = blockIdx.x * 256 + threadIdx.x;      // over T * VD/4
    int t = idx / (VD/4);
    if (t >= T_LEN) return;
    int c = (idx - t * (VD/4)) * 4;
    float d[4];
    #pragma unroll
    for (int j = 0; j < 4; j++) d[j] = dyn[t*4 + j];
    float a0 = 0.f, a1 = 0.f, a2 = 0.f, a3 = 0.f;
    #pragma unroll
    for (int j = 0; j < 4; j++) {
        int tt = t + j - 3;
        if (tt >= 0) {
            float4 xv = *(const float4*)(x + (size_t)tt * VD + c);
            a0 += (cw[(c+0)*4 + j] + d[j]) * xv.x;
            a1 += (cw[(c+1)*4 + j] + d[j]) * xv.y;
            a2 += (cw[(c+2)*4 + j] + d[j]) * xv.z;
            a3 += (cw[(c+3)*4 + j] + d[j]) * xv.w;
        }
    }
    float4 r;
    r.x = siluf(a0); r.y = siluf(a1); r.z = siluf(a2); r.w = siluf(a3);
    *(float4*)(v + (size_t)t * VD + c) = r;
}

// ---------------- L2 norm per 256-dim vector, optional extra scale ----------------
__global__ __launch_bounds__(256)
void l2norm_scale_kernel(float* __restrict__ p, float mul) {
    int vec  = blockIdx.x * 8 + (threadIdx.x >> 5);
    int lane = threadIdx.x & 31;
    float* r = p + (size_t)vec * DKDIM;
    float x[8];
    float ss = 0.f;
    #pragma unroll
    for (int i = 0; i < 8; i++) { x[i] = r[lane + 32*i]; ss += x[i]*x[i]; }
    #pragma unroll
    for (int off = 16; off; off >>= 1) ss += __shfl_xor_sync(0xffffffffu, ss, off);
    float s = rsqrtf(ss + 1e-6f) * mul;
    #pragma unroll
    for (int i = 0; i < 8; i++) r[lane + 32*i] = x[i] * s;
}

// ---------------- the sequential gated delta-rule scan ----------------
// Columns of S (per head, DV=512 each, 3072 total) evolve independently.
// Block = 128 threads (4 warps). Each warp owns 2 columns; block owns 8
// consecutive columns of one head. q/k for the head are staged through
// double-buffered SMEM (one barrier per step).
__global__ __launch_bounds__(128)
void scan_kernel(const float* __restrict__ q, const float* __restrict__ k,
                 const float* __restrict__ v, const float* __restrict__ eg,
                 const float* __restrict__ beta, float* __restrict__ o) {
    const int cc0  = blockIdx.x * 8;       // flat column base (head*512 + col)
    const int head = cc0 >> 9;
    const int tid  = threadIdx.x;
    const int w    = tid >> 5, lane = tid & 31;
    const int c0   = cc0 + 2*w;

    __shared__ float sq[2][256];
    __shared__ float sk[2][256];
    __shared__ float sv[2][8];
    __shared__ float seb[2][2];

    float s0[8], s1[8];
    #pragma unroll
    for (int i = 0; i < 8; i++) { s0[i] = 0.f; s1[i] = 0.f; }

    const float* qrow = q + head * DKDIM;
    const float* krow = k + head * DKDIM;

    auto stage = [&](int b, int t) {
        size_t qo = (size_t)t * KD;
        sq[b][tid]       = qrow[qo + tid];
        sq[b][tid + 128] = qrow[qo + tid + 128];
        sk[b][tid]       = krow[qo + tid];
        sk[b][tid + 128] = krow[qo + tid + 128];
        if (tid < 8)       sv[b][tid] = v[(size_t)t * VD + cc0 + tid];
        else if (tid == 8) seb[b][0] = eg[t*6 + head];
        else if (tid == 9) seb[b][1] = beta[t*6 + head];
    };

    stage(0, 0);
    for (int t = 0; t < T_LEN; ++t) {
        int cur = t & 1;
        __syncthreads();
        if (t + 1 < T_LEN) stage(cur ^ 1, t + 1);

        float egv = seb[cur][0], bt = seb[cur][1];
        float kx[8];
        #pragma unroll
        for (int i = 0; i < 8; i++) kx[i] = sk[cur][lane + 32*i];

        float d0 = 0.f, d1 = 0.f;
        #pragma unroll
        for (int i = 0; i < 8; i++) {
            s0[i] *= egv; d0 += kx[i] * s0[i];
            s1[i] *= egv; d1 += kx[i] * s1[i];
        }
        #pragma unroll
        for (int off = 16; off; off >>= 1) {
            d0 += __shfl_xor_sync(0xffffffffu, d0, off);
            d1 += __shfl_xor_sync(0xffffffffu, d1, off);
        }
        float dv0 = (sv[cur][2*w]     - d0) * bt;
        float dv1 = (sv[cur][2*w + 1] - d1) * bt;

        float e0 = 0.f, e1 = 0.f;
        #pragma unroll
        for (int i = 0; i < 8; i++) {
            float qx = sq[cur][lane + 32*i];
            s0[i] += kx[i] * dv0; e0 += qx * s0[i];
            s1[i] += kx[i] * dv1; e1 += qx * s1[i];
        }
        #pragma unroll
        for (int off = 16; off; off >>= 1) {
            e0 += __shfl_xor_sync(0xffffffffu, e0, off);
            e1 += __shfl_xor_sync(0xffffffffu, e1, off);
        }
        if (lane == 0) {
            o[(size_t)t * VD + c0]     = e0;   // scale folded into q
            o[(size_t)t * VD + c0 + 1] = e1;
        }
    }
}

// ---------------- gated RMSNorm: y = o * rsqrt(mean(o^2)+eps) * nw * silu(gate) ----------------
__global__ __launch_bounds__(128)
void rmsnorm_gate_kernel(const float* __restrict__ o, const float* __restrict__ gate,
                         const float* __restrict__ nw, float* __restrict__ y) {
    int row = blockIdx.x;                  // t*6 + h
    int tid = threadIdx.x;
    size_t base = (size_t)(row / 6) * VD + (size_t)(row % 6) * DVDIM;
    float4 ov = *(const float4*)(o + base + tid*4);
    float ss = ov.x*ov.x + ov.y*ov.y + ov.z*ov.z + ov.w*ov.w;
    #pragma unroll
    for (int off = 16; off; off >>= 1) ss += __shfl_xor_sync(0xffffffffu, ss, off);
    __shared__ float red[4];
    int w = tid >> 5, lane = tid & 31;
    if (lane == 0) red[w] = ss;
    __syncthreads();
    float tot = red[0] + red[1] + red[2] + red[3];
    float rms = rsqrtf(tot * (1.0f / (float)DVDIM) + 1e-5f);
    float4 gv = *(const float4*)(gate + base + tid*4);
    float4 nv = *(const float4*)(nw + tid*4);
    float4 r;
    r.x = ov.x * rms * nv.x * siluf(gv.x);
    r.y = ov.y * rms * nv.y * siluf(gv.y);
    r.z = ov.z * rms * nv.z * siluf(gv.z);
    r.w = ov.w * rms * nv.w * siluf(gv.w);
    *(float4*)(y + base + tid*4) = r;
}

// ---------------- launch ----------------
extern "C" void kernel_launch(void* const* d_in, const int* in_sizes, int n_in,
                              void* d_out, int out_size) {
    const float* h       = (const float*)d_in[0];
    const float* Wq      = (const float*)d_in[1];
    const float* Wk      = (const float*)d_in[2];
    const float* Wv      = (const float*)d_in[3];
    const float* Wb      = (const float*)d_in[4];
    const float* Wa      = (const float*)d_in[5];
    const float* Wg      = (const float*)d_in[6];
    const float* Wo      = (const float*)d_in[7];
    const float* A_log   = (const float*)d_in[8];
    const float* dt_bias = (const float*)d_in[9];
    const float* conv_w  = (const float*)d_in[10];
    const float* gen_w1  = (const float*)d_in[11];
    const float* gen_w2  = (const float*)d_in[12];
    const float* norm_w  = (const float*)d_in[13];
    float* out = (float*)d_out;

    float *pq, *pk, *px, *pv, *pd1, *pd, *peg, *pbeta, *pgate, *po;
    cudaGetSymbolAddress((void**)&pq,    g_q);
    cudaGetSymbolAddress((void**)&pk,    g_k);
    cudaGetSymbolAddress((void**)&px,    g_x);
    cudaGetSymbolAddress((void**)&pv,    g_v);
    cudaGetSymbolAddress((void**)&pd1,   g_dyn1);
    cudaGetSymbolAddress((void**)&pd,    g_dyn);
    cudaGetSymbolAddress((void**)&peg,   g_eg);
    cudaGetSymbolAddress((void**)&pbeta, g_beta);
    cudaGetSymbolAddress((void**)&pgate, g_gate);
    cudaGetSymbolAddress((void**)&po,    g_o);

    // projections
    sgemm_kernel<1><<<dim3(KD/128,  T_LEN/128), 256>>>(h, Wq,     pq,    T_LEN, KD,   D_DIM);
    sgemm_kernel<1><<<dim3(KD/128,  T_LEN/128), 256>>>(h, Wk,     pk,    T_LEN, KD,   D_DIM);
    sgemm_kernel<0><<<dim3(VD/128,  T_LEN/128), 256>>>(h, Wv,     px,    T_LEN, VD,   D_DIM);
    sgemm_kernel<1><<<dim3(GENW/128,T_LEN/128), 256>>>(h, gen_w1, pd1,   T_LEN, GENW, D_DIM);
    sgemm_kernel<0><<<dim3(VD/128,  T_LEN/128), 256>>>(h, Wg,     pgate, T_LEN, VD,   D_DIM);

    dyn2_kernel<<<T_LEN/8, 256>>>(pd1, gen_w2, pd);
    betag_kernel<<<T_LEN, 256>>>(h, Wb, Wa, A_log, dt_bias, pbeta, peg);
    conv_silu_kernel<<<(T_LEN*(VD/4))/256, 256>>>(px, pd, conv_w, pv);

    l2norm_scale_kernel<<<(T_LEN*H_N)/8, 256>>>(pq, 0.0625f);  // fold DK^-0.5 into q
    l2norm_scale_kernel<<<(T_LEN*H_N)/8, 256>>>(pk, 1.0f);

    scan_kernel<<<VD/8, 128>>>(pq, pk, pv, peg, pbeta, po);

    rmsnorm_gate_kernel<<<T_LEN*H_N, 128>>>(po, pgate, norm_w, px);  // reuse g_x as y

    // out = y @ Wo
    sgemm_kernel<0><<<dim3(D_DIM/128, T_LEN/128), 256>>>(px, Wo, out, T_LEN, D_DIM, VD);
}

// round 2
// speedup vs baseline: 1.4272x; 1.4272x over previous
#include <cuda_runtime.h>
#include <cstdint>

// ---------------- problem constants ----------------
#define T_LEN 4096
#define D_DIM 2048
#define H_N   6
#define DKDIM 256
#define DVDIM 512
#define KD    1536   // H_N*DKDIM
#define VD    3072   // H_N*DVDIM
#define GENW  256
#define KSZ   4

// ---------------- scratch (static device, allocation-free) ----------------
__device__ float g_q[(size_t)T_LEN*KD];
__device__ float g_k[(size_t)T_LEN*KD];
__device__ float g_x[(size_t)T_LEN*VD];      // x = h@Wv, later reused as y (post-rmsnorm)
__device__ float g_v[(size_t)T_LEN*VD];      // conv+silu output
__device__ float g_dyn1[(size_t)T_LEN*GENW];
__device__ float g_dyn[(size_t)T_LEN*4];
__device__ float g_eg[(size_t)T_LEN*H_N];    // exp(g)
__device__ float g_beta[(size_t)T_LEN*H_N];
__device__ float g_gate[(size_t)T_LEN*VD];
__device__ float g_o[(size_t)T_LEN*VD];      // scan output

__device__ __forceinline__ float siluf(float x) { return x / (1.0f + expf(-x)); }

__device__ __forceinline__ uint32_t f2tf32(float x) {
    uint32_t u;
    asm("cvt.rna.tf32.f32 %0, %1;" : "=r"(u) : "f"(x));
    return u;
}

// ---------------- TF32 tensor-core GEMM ----------------
// C[M,N] = act(A[M,K] @ B[K,N]), row-major. BM=BN=128, BK=16, 256 threads
// (8 warps as 4x2; warp tile 32x64 via m16n8k8 tf32 mma, fp32 accumulate).
// Requires M%128==0, N%128==0, K%16==0.
template<int ACT>
__global__ __launch_bounds__(256)
void tf32gemm_kernel(const float* __restrict__ A, const float* __restrict__ B,
                     float* __restrict__ C, int M, int N, int K) {
    __shared__ float As[16][136];   // [k][m], +8 pad => conflict-free frag loads
    __shared__ float Bs[16][136];   // [k][n]

    const int tid  = threadIdx.x;
    const int warp = tid >> 5;
    const int lane = tid & 31;
    const int gid  = lane >> 2;     // 0..7
    const int tig  = lane & 3;      // 0..3
    const int wm   = warp >> 1;     // 0..3  -> warp row tile (32 rows)
    const int wn   = warp & 1;      // 0..1  -> warp col tile (64 cols)

    const int row0 = blockIdx.y * 128;
    const int col0 = blockIdx.x * 128;

    // global-load mapping
    const int aRow = tid >> 1;          // 0..127
    const int aC   = (tid & 1) * 8;     // 0 or 8
    const int bK   = tid >> 5;          // 0..7
    const int bN   = (tid & 31) * 4;    // 0..124

    float acc[2][8][4];
    #pragma unroll
    for (int i = 0; i < 2; i++)
        #pragma unroll
        for (int j = 0; j < 8; j++)
            #pragma unroll
            for (int c = 0; c < 4; c++) acc[i][j][c] = 0.0f;

    const float* Aptr = A + (size_t)(row0 + aRow) * K;
    const float* Bptr = B + col0 + bN;

    for (int k0 = 0; k0 < K; k0 += 16) {
        // ---- stage A (transposed) and B into SMEM, rounding to tf32 ----
        {
            float4 t0 = *(const float4*)(Aptr + k0 + aC);
            float4 t1 = *(const float4*)(Aptr + k0 + aC + 4);
            As[aC+0][aRow] = __uint_as_float(f2tf32(t0.x));
            As[aC+1][aRow] = __uint_as_float(f2tf32(t0.y));
            As[aC+2][aRow] = __uint_as_float(f2tf32(t0.z));
            As[aC+3][aRow] = __uint_as_float(f2tf32(t0.w));
            As[aC+4][aRow] = __uint_as_float(f2tf32(t1.x));
            As[aC+5][aRow] = __uint_as_float(f2tf32(t1.y));
            As[aC+6][aRow] = __uint_as_float(f2tf32(t1.z));
            As[aC+7][aRow] = __uint_as_float(f2tf32(t1.w));

            #pragma unroll
            for (int r = 0; r < 2; ++r) {
                float4 tb = *(const float4*)(Bptr + (size_t)(k0 + bK + 8*r) * N);
                float4 rb;
                rb.x = __uint_as_float(f2tf32(tb.x));
                rb.y = __uint_as_float(f2tf32(tb.y));
                rb.z = __uint_as_float(f2tf32(tb.z));
                rb.w = __uint_as_float(f2tf32(tb.w));
                *(float4*)(&Bs[bK + 8*r][bN]) = rb;
            }
        }
        __syncthreads();

        // ---- 2 k-steps of m16n8k8 ----
        #pragma unroll
        for (int kk = 0; kk < 16; kk += 8) {
            uint32_t af[2][4];
            #pragma unroll
            for (int i = 0; i < 2; ++i) {
                int m = wm*32 + i*16 + gid;
                af[i][0] = __float_as_uint(As[kk + tig    ][m]);
                af[i][1] = __float_as_uint(As[kk + tig    ][m + 8]);
                af[i][2] = __float_as_uint(As[kk + tig + 4][m]);
                af[i][3] = __float_as_uint(As[kk + tig + 4][m + 8]);
            }
            uint32_t bf[8][2];
            #pragma unroll
            for (int j = 0; j < 8; ++j) {
                int n = wn*64 + j*8 + gid;
                bf[j][0] = __float_as_uint(Bs[kk + tig    ][n]);
                bf[j][1] = __float_as_uint(Bs[kk + tig + 4][n]);
            }
            #pragma unroll
            for (int i = 0; i < 2; ++i)
                #pragma unroll
                for (int j = 0; j < 8; ++j) {
                    asm volatile(
                        "mma.sync.aligned.m16n8k8.row.col.f32.tf32.tf32.f32 "
                        "{%0,%1,%2,%3}, {%4,%5,%6,%7}, {%8,%9}, {%0,%1,%2,%3};"
                        : "+f"(acc[i][j][0]), "+f"(acc[i][j][1]),
                          "+f"(acc[i][j][2]), "+f"(acc[i][j][3])
                        : "r"(af[i][0]), "r"(af[i][1]), "r"(af[i][2]), "r"(af[i][3]),
                          "r"(bf[j][0]), "r"(bf[j][1]));
                }
        }
        __syncthreads();
    }

    // ---- epilogue ----
    #pragma unroll
    for (int i = 0; i < 2; ++i) {
        int row = row0 + wm*32 + i*16 + gid;
        #pragma unroll
        for (int j = 0; j < 8; ++j) {
            int col = col0 + wn*64 + j*8 + 2*tig;
            float2 r0, r1;
            r0.x = ACT ? siluf(acc[i][j][0]) : acc[i][j][0];
            r0.y = ACT ? siluf(acc[i][j][1]) : acc[i][j][1];
            r1.x = ACT ? siluf(acc[i][j][2]) : acc[i][j][2];
            r1.y = ACT ? siluf(acc[i][j][3]) : acc[i][j][3];
            *(float2*)(C + (size_t)row * N + col)       = r0;
            *(float2*)(C + (size_t)(row + 8) * N + col) = r1;
        }
    }
}

// ---------------- dyn = dyn1[T,256] @ gen_w2[256,4] (warp per token) ----------------
__global__ __launch_bounds__(256)
void dyn2_kernel(const float* __restrict__ dyn1, const float* __restrict__ w2,
                 float* __restrict__ dyn) {
    int t    = blockIdx.x * 8 + (threadIdx.x >> 5);
    int lane = threadIdx.x & 31;
    const float* r = dyn1 + (size_t)t * GENW;
    float a0 = 0.f, a1 = 0.f, a2 = 0.f, a3 = 0.f;
    #pragma unroll
    for (int i = 0; i < 8; i++) {
        int d = lane + 32*i;
        float v = r[d];
        const float* w = w2 + d*4;
        a0 += v*w[0]; a1 += v*w[1]; a2 += v*w[2]; a3 += v*w[3];
    }
    #pragma unroll
    for (int off = 16; off; off >>= 1) {
        a0 += __shfl_xor_sync(0xffffffffu, a0, off);
        a1 += __shfl_xor_sync(0xffffffffu, a1, off);
        a2 += __shfl_xor_sync(0xffffffffu, a2, off);
        a3 += __shfl_xor_sync(0xffffffffu, a3, off);
    }
    if (lane == 0) {
        dyn[t*4+0] = a0; dyn[t*4+1] = a1; dyn[t*4+2] = a2; dyn[t*4+3] = a3;
    }
}

// ---------------- beta = sigmoid(h@Wb), eg = exp(-exp(A_log)*softplus(h@Wa+dt_bias)) ----------------
__global__ __launch_bounds__(256)
void betag_kernel(const float* __restrict__ h, const float* __restrict__ Wb,
                  const float* __restrict__ Wa, const float* __restrict__ A_log,
                  const float* __restrict__ dt_bias,
                  float* __restrict__ beta, float* __restrict__ eg) {
    int t = blockIdx.x;
    const float* hr = h + (size_t)t * D_DIM;
    float acc[12];
    #pragma unroll
    for (int j = 0; j < 12; j++) acc[j] = 0.f;
    for (int d = threadIdx.x; d < D_DIM; d += 256) {
        float hv = hr[d];
        const float* wb = Wb + d*6;
        const float* wa = Wa + d*6;
        #pragma unroll
        for (int j = 0; j < 6; j++) {
            acc[j]   += hv * wb[j];
            acc[6+j] += hv * wa[j];
        }
    }
    #pragma unroll
    for (int j = 0; j < 12; j++)
        #pragma unroll
        for (int off = 16; off; off >>= 1)
            acc[j] += __shfl_xor_sync(0xffffffffu, acc[j], off);

    __shared__ float red[8][12];
    int w = threadIdx.x >> 5, lane = threadIdx.x & 31;
    if (lane == 0) {
        #pragma unroll
        for (int j = 0; j < 12; j++) red[w][j] = acc[j];
    }
    __syncthreads();
    if (threadIdx.x < 12) {
        float s = 0.f;
        #pragma unroll
        for (int i = 0; i < 8; i++) s += red[i][threadIdx.x];
        int j = threadIdx.x;
        if (j < 6) {
            beta[t*6 + j] = 1.0f / (1.0f + expf(-s));
        } else {
            int hh = j - 6;
            float xx = s + dt_bias[hh];
            float sp = (xx > 20.0f) ? xx : log1pf(expf(xx));
            float g  = -expf(A_log[hh]) * sp;
            eg[t*6 + hh] = expf(g);
        }
    }
}

// ---------------- dynamic short conv + silu ----------------
__global__ __launch_bounds__(256)
void conv_silu_kernel(const float* __restrict__ x, const float* __restrict__ dyn,
                      const float* __restrict__ cw, float* __restrict__ v) {
    int idx = blockIdx.x * 256 + threadIdx.x;      // over T * VD/4
    int t = idx / (VD/4);
    if (t >= T_LEN) return;
    int c = (idx - t * (VD/4)) * 4;
    float d[4];
    #pragma unroll
    for (int j = 0; j < 4; j++) d[j] = dyn[t*4 + j];
    float a0 = 0.f, a1 = 0.f, a2 = 0.f, a3 = 0.f;
    #pragma unroll
    for (int j = 0; j < 4; j++) {
        int tt = t + j - 3;
        if (tt >= 0) {
            float4 xv = *(const float4*)(x + (size_t)tt * VD + c);
            a0 += (cw[(c+0)*4 + j] + d[j]) * xv.x;
            a1 += (cw[(c+1)*4 + j] + d[j]) * xv.y;
            a2 += (cw[(c+2)*4 + j] + d[j]) * xv.z;
            a3 += (cw[(c+3)*4 + j] + d[j]) * xv.w;
        }
    }
    float4 r;
    r.x = siluf(a0); r.y = siluf(a1); r.z = siluf(a2); r.w = siluf(a3);
    *(float4*)(v + (size_t)t * VD + c) = r;
}

// ---------------- L2 norm per 256-dim vector, optional extra scale ----------------
__global__ __launch_bounds__(256)
void l2norm_scale_kernel(float* __restrict__ p, float mul) {
    int vec  = blockIdx.x * 8 + (threadIdx.x >> 5);
    int lane = threadIdx.x & 31;
    float* r = p + (size_t)vec * DKDIM;
    float x[8];
    float ss = 0.f;
    #pragma unroll
    for (int i = 0; i < 8; i++) { x[i] = r[lane + 32*i]; ss += x[i]*x[i]; }
    #pragma unroll
    for (int off = 16; off; off >>= 1) ss += __shfl_xor_sync(0xffffffffu, ss, off);
    float s = rsqrtf(ss + 1e-6f) * mul;
    #pragma unroll
    for (int i = 0; i < 8; i++) r[lane + 32*i] = x[i] * s;
}

// ---------------- the sequential gated delta-rule scan ----------------
__global__ __launch_bounds__(128)
void scan_kernel(const float* __restrict__ q, const float* __restrict__ k,
                 const float* __restrict__ v, const float* __restrict__ eg,
                 const float* __restrict__ beta, float* __restrict__ o) {
    const int cc0  = blockIdx.x * 8;       // flat column base (head*512 + col)
    const int head = cc0 >> 9;
    const int tid  = threadIdx.x;
    const int w    = tid >> 5, lane = tid & 31;
    const int c0   = cc0 + 2*w;

    __shared__ float sq[2][256];
    __shared__ float sk[2][256];
    __shared__ float sv[2][8];
    __shared__ float seb[2][2];

    float s0[8], s1[8];
    #pragma unroll
    for (int i = 0; i < 8; i++) { s0[i] = 0.f; s1[i] = 0.f; }

    const float* qrow = q + head * DKDIM;
    const float* krow = k + head * DKDIM;

    auto stage = [&](int b, int t) {
        size_t qo = (size_t)t * KD;
        sq[b][tid]       = qrow[qo + tid];
        sq[b][tid + 128] = qrow[qo + tid + 128];
        sk[b][tid]       = krow[qo + tid];
        sk[b][tid + 128] = krow[qo + tid + 128];
        if (tid < 8)       sv[b][tid] = v[(size_t)t * VD + cc0 + tid];
        else if (tid == 8) seb[b][0] = eg[t*6 + head];
        else if (tid == 9) seb[b][1] = beta[t*6 + head];
    };

    stage(0, 0);
    for (int t = 0; t < T_LEN; ++t) {
        int cur = t & 1;
        __syncthreads();
        if (t + 1 < T_LEN) stage(cur ^ 1, t + 1);

        float egv = seb[cur][0], bt = seb[cur][1];
        float kx[8];
        #pragma unroll
        for (int i = 0; i < 8; i++) kx[i] = sk[cur][lane + 32*i];

        float d0 = 0.f, d1 = 0.f;
        #pragma unroll
        for (int i = 0; i < 8; i++) {
            s0[i] *= egv; d0 += kx[i] * s0[i];
            s1[i] *= egv; d1 += kx[i] * s1[i];
        }
        #pragma unroll
        for (int off = 16; off; off >>= 1) {
            d0 += __shfl_xor_sync(0xffffffffu, d0, off);
            d1 += __shfl_xor_sync(0xffffffffu, d1, off);
        }
        float dv0 = (sv[cur][2*w]     - d0) * bt;
        float dv1 = (sv[cur][2*w + 1] - d1) * bt;

        float e0 = 0.f, e1 = 0.f;
        #pragma unroll
        for (int i = 0; i < 8; i++) {
            float qx = sq[cur][lane + 32*i];
            s0[i] += kx[i] * dv0; e0 += qx * s0[i];
            s1[i] += kx[i] * dv1; e1 += qx * s1[i];
        }
        #pragma unroll
        for (int off = 16; off; off >>= 1) {
            e0 += __shfl_xor_sync(0xffffffffu, e0, off);
            e1 += __shfl_xor_sync(0xffffffffu, e1, off);
        }
        if (lane == 0) {
            o[(size_t)t * VD + c0]     = e0;   // scale folded into q
            o[(size_t)t * VD + c0 + 1] = e1;
        }
    }
}

// ---------------- gated RMSNorm: y = o * rsqrt(mean(o^2)+eps) * nw * silu(gate) ----------------
__global__ __launch_bounds__(128)
void rmsnorm_gate_kernel(const float* __restrict__ o, const float* __restrict__ gate,
                         const float* __restrict__ nw, float* __restrict__ y) {
    int row = blockIdx.x;                  // t*6 + h
    int tid = threadIdx.x;
    size_t base = (size_t)(row / 6) * VD + (size_t)(row % 6) * DVDIM;
    float4 ov = *(const float4*)(o + base + tid*4);
    float ss = ov.x*ov.x + ov.y*ov.y + ov.z*ov.z + ov.w*ov.w;
    #pragma unroll
    for (int off = 16; off; off >>= 1) ss += __shfl_xor_sync(0xffffffffu, ss, off);
    __shared__ float red[4];
    int w = tid >> 5, lane = tid & 31;
    if (lane == 0) red[w] = ss;
    __syncthreads();
    float tot = red[0] + red[1] + red[2] + red[3];
    float rms = rsqrtf(tot * (1.0f / (float)DVDIM) + 1e-5f);
    float4 gv = *(const float4*)(gate + base + tid*4);
    float4 nv = *(const float4*)(nw + tid*4);
    float4 r;
    r.x = ov.x * rms * nv.x * siluf(gv.x);
    r.y = ov.y * rms * nv.y * siluf(gv.y);
    r.z = ov.z * rms * nv.z * siluf(gv.z);
    r.w = ov.w * rms * nv.w * siluf(gv.w);
    *(float4*)(y + base + tid*4) = r;
}

// ---------------- launch ----------------
extern "C" void kernel_launch(void* const* d_in, const int* in_sizes, int n_in,
                              void* d_out, int out_size) {
    const float* h       = (const float*)d_in[0];
    const float* Wq      = (const float*)d_in[1];
    const float* Wk      = (const float*)d_in[2];
    const float* Wv      = (const float*)d_in[3];
    const float* Wb      = (const float*)d_in[4];
    const float* Wa      = (const float*)d_in[5];
    const float* Wg      = (const float*)d_in[6];
    const float* Wo      = (const float*)d_in[7];
    const float* A_log   = (const float*)d_in[8];
    const float* dt_bias = (const float*)d_in[9];
    const float* conv_w  = (const float*)d_in[10];
    const float* gen_w1  = (const float*)d_in[11];
    const float* gen_w2  = (const float*)d_in[12];
    const float* norm_w  = (const float*)d_in[13];
    float* out = (float*)d_out;

    float *pq, *pk, *px, *pv, *pd1, *pd, *peg, *pbeta, *pgate, *po;
    cudaGetSymbolAddress((void**)&pq,    g_q);
    cudaGetSymbolAddress((void**)&pk,    g_k);
    cudaGetSymbolAddress((void**)&px,    g_x);
    cudaGetSymbolAddress((void**)&pv,    g_v);
    cudaGetSymbolAddress((void**)&pd1,   g_dyn1);
    cudaGetSymbolAddress((void**)&pd,    g_dyn);
    cudaGetSymbolAddress((void**)&peg,   g_eg);
    cudaGetSymbolAddress((void**)&pbeta, g_beta);
    cudaGetSymbolAddress((void**)&pgate, g_gate);
    cudaGetSymbolAddress((void**)&po,    g_o);

    // projections (tf32 tensor cores)
    tf32gemm_kernel<1><<<dim3(KD/128,  T_LEN/128), 256>>>(h, Wq,     pq,    T_LEN, KD,   D_DIM);
    tf32gemm_kernel<1><<<dim3(KD/128,  T_LEN/128), 256>>>(h, Wk,     pk,    T_LEN, KD,   D_DIM);
    tf32gemm_kernel<0><<<dim3(VD/128,  T_LEN/128), 256>>>(h, Wv,     px,    T_LEN, VD,   D_DIM);
    tf32gemm_kernel<1><<<dim3(GENW/128,T_LEN/128), 256>>>(h, gen_w1, pd1,   T_LEN, GENW, D_DIM);
    tf32gemm_kernel<0><<<dim3(VD/128,  T_LEN/128), 256>>>(h, Wg,     pgate, T_LEN, VD,   D_DIM);

    dyn2_kernel<<<T_LEN/8, 256>>>(pd1, gen_w2, pd);
    betag_kernel<<<T_LEN, 256>>>(h, Wb, Wa, A_log, dt_bias, pbeta, peg);
    conv_silu_kernel<<<(T_LEN*(VD/4))/256, 256>>>(px, pd, conv_w, pv);

    l2norm_scale_kernel<<<(T_LEN*H_N)/8, 256>>>(pq, 0.0625f);  // fold DK^-0.5 into q
    l2norm_scale_kernel<<<(T_LEN*H_N)/8, 256>>>(pk, 1.0f);

    scan_kernel<<<VD/8, 128>>>(pq, pk, pv, peg, pbeta, po);

    rmsnorm_gate_kernel<<<T_LEN*H_N, 128>>>(po, pgate, norm_w, px);  // reuse g_x as y

    // out = y @ Wo
    tf32gemm_kernel<0><<<dim3(D_DIM/128, T_LEN/128), 256>>>(px, Wo, out, T_LEN, D_DIM, VD);
}

// round 3
// speedup vs baseline: 2.6388x; 1.8489x over previous
#include <cuda_runtime.h>
#include <cstdint>

// ---------------- problem constants ----------------
#define T_LEN 4096
#define D_DIM 2048
#define H_N   6
#define DKDIM 256
#define DVDIM 512
#define KD    1536   // H_N*DKDIM
#define VD    3072   // H_N*DVDIM
#define GENW  256
#define KSZ   4

// ---------------- scratch (static device, allocation-free) ----------------
__device__ float g_q[(size_t)T_LEN*KD];
__device__ float g_k[(size_t)T_LEN*KD];
__device__ float g_x[(size_t)T_LEN*VD];      // x = h@Wv; later reused as y (tf32-rounded)
__device__ float g_v[(size_t)T_LEN*VD];      // conv+silu output
__device__ float g_dyn1[(size_t)T_LEN*GENW];
__device__ float g_dyn[(size_t)T_LEN*4];
__device__ float g_eg[(size_t)T_LEN*H_N];    // exp(g)
__device__ float g_beta[(size_t)T_LEN*H_N];
__device__ float g_gate[(size_t)T_LEN*VD];
__device__ float g_o[(size_t)T_LEN*VD];      // scan output
__device__ float g_qk[(size_t)T_LEN*H_N];    // q·k per (t,head), post-norm

// tf32-pre-rounded copies (GEMM operands)
__device__ float g_hr [(size_t)T_LEN*D_DIM];
__device__ float g_wqr[(size_t)D_DIM*KD];
__device__ float g_wkr[(size_t)D_DIM*KD];
__device__ float g_wvr[(size_t)D_DIM*VD];
__device__ float g_wgr[(size_t)D_DIM*VD];
__device__ float g_g1r[(size_t)D_DIM*GENW];
__device__ float g_wor[(size_t)VD*D_DIM];

__device__ __forceinline__ float siluf(float x) { return x / (1.0f + expf(-x)); }

__device__ __forceinline__ float f2tf32f(float x) {
    uint32_t u;
    asm("cvt.rna.tf32.f32 %0, %1;" : "=r"(u) : "f"(x));
    return __uint_as_float(u);
}

// ---------------- tf32 pre-round copy ----------------
__global__ __launch_bounds__(256)
void round_kernel(const float* __restrict__ s, float* __restrict__ d, int n4) {
    int i = blockIdx.x * 256 + threadIdx.x;
    if (i < n4) {
        float4 v = ((const float4*)s)[i];
        v.x = f2tf32f(v.x); v.y = f2tf32f(v.y);
        v.z = f2tf32f(v.z); v.w = f2tf32f(v.w);
        ((float4*)d)[i] = v;
    }
}

// ---------------- cp.async helpers ----------------
__device__ __forceinline__ void cp16(void* smem, const void* gmem) {
    uint32_t sa = (uint32_t)__cvta_generic_to_shared(smem);
    asm volatile("cp.async.cg.shared.global [%0], [%1], 16;" :: "r"(sa), "l"(gmem) : "memory");
}

// ---------------- tf32 tensor-core GEMM body ----------------
// C[M,N] tile = act(A[.,K] @ B[K,Nseg]), inputs pre-rounded to tf32.
// BM=BN=128, BK=16, 256 threads, 2-stage cp.async pipeline.
__device__ __forceinline__ void gemm_body(
    const float* __restrict__ A, const float* __restrict__ B, float* __restrict__ C,
    int K, int Nseg, int row0, int col0, int act)
{
    __shared__ float As[2][128][20];   // [stage][m][k] pad->20 (conflict-free frags)
    __shared__ float Bs[2][16][136];   // [stage][k][n] pad->136

    const int tid  = threadIdx.x;
    const int warp = tid >> 5, lane = tid & 31;
    const int gid  = lane >> 2, tig  = lane & 3;
    const int wm   = warp >> 1, wn   = warp & 1;

    const int aRow = tid >> 1, aC = (tid & 1) * 8;
    const int bKr  = tid >> 4, bN = (tid & 15) * 8;

    const float* Ab = A + (size_t)(row0 + aRow) * K + aC;
    const float* Bb = B + (size_t)bKr * Nseg + col0 + bN;

    float acc[2][8][4];
    #pragma unroll
    for (int i = 0; i < 2; i++)
        #pragma unroll
        for (int j = 0; j < 8; j++)
            #pragma unroll
            for (int c = 0; c < 4; c++) acc[i][j][c] = 0.0f;

    auto issue = [&](int st, int k0) {
        cp16(&As[st][aRow][aC],     Ab + k0);
        cp16(&As[st][aRow][aC + 4], Ab + k0 + 4);
        cp16(&Bs[st][bKr][bN],      Bb + (size_t)k0 * Nseg);
        cp16(&Bs[st][bKr][bN + 4],  Bb + (size_t)k0 * Nseg + 4);
        asm volatile("cp.async.commit_group;" ::: "memory");
    };

    const int KT = K >> 4;
    issue(0, 0);
    for (int kt = 0; kt < KT; ++kt) {
        const int cur = kt & 1;
        asm volatile("cp.async.wait_group 0;" ::: "memory");
        __syncthreads();
        if (kt + 1 < KT) issue(cur ^ 1, (kt + 1) * 16);

        #pragma unroll
        for (int kk = 0; kk < 16; kk += 8) {
            uint32_t af[2][4];
            #pragma unroll
            for (int i = 0; i < 2; ++i) {
                int m = wm*32 + i*16 + gid;
                af[i][0] = __float_as_uint(As[cur][m    ][kk + tig]);
                af[i][1] = __float_as_uint(As[cur][m + 8][kk + tig]);
                af[i][2] = __float_as_uint(As[cur][m    ][kk + tig + 4]);
                af[i][3] = __float_as_uint(As[cur][m + 8][kk + tig + 4]);
            }
            uint32_t bf[8][2];
            #pragma unroll
            for (int j = 0; j < 8; ++j) {
                int n = wn*64 + j*8 + gid;
                bf[j][0] = __float_as_uint(Bs[cur][kk + tig    ][n]);
                bf[j][1] = __float_as_uint(Bs[cur][kk + tig + 4][n]);
            }
            #pragma unroll
            for (int i = 0; i < 2; ++i)
                #pragma unroll
                for (int j = 0; j < 8; ++j) {
                    asm volatile(
                        "mma.sync.aligned.m16n8k8.row.col.f32.tf32.tf32.f32 "
                        "{%0,%1,%2,%3}, {%4,%5,%6,%7}, {%8,%9}, {%0,%1,%2,%3};"
                        : "+f"(acc[i][j][0]), "+f"(acc[i][j][1]),
                          "+f"(acc[i][j][2]), "+f"(acc[i][j][3])
                        : "r"(af[i][0]), "r"(af[i][1]), "r"(af[i][2]), "r"(af[i][3]),
                          "r"(bf[j][0]), "r"(bf[j][1]));
                }
        }
    }

    #pragma unroll
    for (int i = 0; i < 2; ++i) {
        int row = row0 + wm*32 + i*16 + gid;
        #pragma unroll
        for (int j = 0; j < 8; ++j) {
            int col = col0 + wn*64 + j*8 + 2*tig;
            float v0 = acc[i][j][0], v1 = acc[i][j][1];
            float v2 = acc[i][j][2], v3 = acc[i][j][3];
            if (act) { v0 = siluf(v0); v1 = siluf(v1); v2 = siluf(v2); v3 = siluf(v3); }
            *(float2*)(C + (size_t)row * Nseg + col)       = make_float2(v0, v1);
            *(float2*)(C + (size_t)(row + 8) * Nseg + col) = make_float2(v2, v3);
        }
    }
}

// ---------------- fused projection GEMM: Wq|Wk|Wv|Wg|gen_w1 ----------------
__global__ __launch_bounds__(256)
void proj_gemm_kernel(const float* __restrict__ hR,
                      const float* __restrict__ WqR, const float* __restrict__ WkR,
                      const float* __restrict__ WvR, const float* __restrict__ WgR,
                      const float* __restrict__ g1R,
                      float* __restrict__ q, float* __restrict__ k,
                      float* __restrict__ x, float* __restrict__ g,
                      float* __restrict__ d1) {
    const int nt = blockIdx.x;   // 0..73 tile column
    const float* B; float* C; int Nseg, col0, act;
    if (nt < 12)      { B = WqR; C = q;  Nseg = KD;   col0 = nt*128;        act = 1; }
    else if (nt < 24) { B = WkR; C = k;  Nseg = KD;   col0 = (nt-12)*128;   act = 1; }
    else if (nt < 48) { B = WvR; C = x;  Nseg = VD;   col0 = (nt-24)*128;   act = 0; }
    else if (nt < 72) { B = WgR; C = g;  Nseg = VD;   col0 = (nt-48)*128;   act = 0; }
    else              { B = g1R; C = d1; Nseg = GENW; col0 = (nt-72)*128;   act = 1; }
    gemm_body(hR, B, C, D_DIM, Nseg, blockIdx.y * 128, col0, act);
}

// ---------------- output GEMM: out = y @ Wo ----------------
__global__ __launch_bounds__(256)
void wo_gemm_kernel(const float* __restrict__ yR, const float* __restrict__ WoR,
                    float* __restrict__ out) {
    gemm_body(yR, WoR, out, VD, D_DIM, blockIdx.y * 128, blockIdx.x * 128, 0);
}

// ---------------- dyn = dyn1[T,256] @ gen_w2[256,4] (warp per token) ----------------
__global__ __launch_bounds__(256)
void dyn2_kernel(const float* __restrict__ dyn1, const float* __restrict__ w2,
                 float* __restrict__ dyn) {
    int t    = blockIdx.x * 8 + (threadIdx.x >> 5);
    int lane = threadIdx.x & 31;
    const float* r = dyn1 + (size_t)t * GENW;
    float a0 = 0.f, a1 = 0.f, a2 = 0.f, a3 = 0.f;
    #pragma unroll
    for (int i = 0; i < 8; i++) {
        int d = lane + 32*i;
        float v = r[d];
        const float* w = w2 + d*4;
        a0 += v*w[0]; a1 += v*w[1]; a2 += v*w[2]; a3 += v*w[3];
    }
    #pragma unroll
    for (int off = 16; off; off >>= 1) {
        a0 += __shfl_xor_sync(0xffffffffu, a0, off);
        a1 += __shfl_xor_sync(0xffffffffu, a1, off);
        a2 += __shfl_xor_sync(0xffffffffu, a2, off);
        a3 += __shfl_xor_sync(0xffffffffu, a3, off);
    }
    if (lane == 0) {
        dyn[t*4+0] = a0; dyn[t*4+1] = a1; dyn[t*4+2] = a2; dyn[t*4+3] = a3;
    }
}

// ---------------- beta = sigmoid(h@Wb), eg = exp(-exp(A_log)*softplus(h@Wa+dt_bias)) ----------------
__global__ __launch_bounds__(256)
void betag_kernel(const float* __restrict__ h, const float* __restrict__ Wb,
                  const float* __restrict__ Wa, const float* __restrict__ A_log,
                  const float* __restrict__ dt_bias,
                  float* __restrict__ beta, float* __restrict__ eg) {
    int t = blockIdx.x;
    const float* hr = h + (size_t)t * D_DIM;
    float acc[12];
    #pragma unroll
    for (int j = 0; j < 12; j++) acc[j] = 0.f;
    for (int d = threadIdx.x; d < D_DIM; d += 256) {
        float hv = hr[d];
        const float* wb = Wb + d*6;
        const float* wa = Wa + d*6;
        #pragma unroll
        for (int j = 0; j < 6; j++) {
            acc[j]   += hv * wb[j];
            acc[6+j] += hv * wa[j];
        }
    }
    #pragma unroll
    for (int j = 0; j < 12; j++)
        #pragma unroll
        for (int off = 16; off; off >>= 1)
            acc[j] += __shfl_xor_sync(0xffffffffu, acc[j], off);

    __shared__ float red[8][12];
    int w = threadIdx.x >> 5, lane = threadIdx.x & 31;
    if (lane == 0) {
        #pragma unroll
        for (int j = 0; j < 12; j++) red[w][j] = acc[j];
    }
    __syncthreads();
    if (threadIdx.x < 12) {
        float s = 0.f;
        #pragma unroll
        for (int i = 0; i < 8; i++) s += red[i][threadIdx.x];
        int j = threadIdx.x;
        if (j < 6) {
            beta[t*6 + j] = 1.0f / (1.0f + expf(-s));
        } else {
            int hh = j - 6;
            float xx = s + dt_bias[hh];
            float sp = (xx > 20.0f) ? xx : log1pf(expf(xx));
            float g  = -expf(A_log[hh]) * sp;
            eg[t*6 + hh] = expf(g);
        }
    }
}

// ---------------- dynamic short conv + silu ----------------
__global__ __launch_bounds__(256)
void conv_silu_kernel(const float* __restrict__ x, const float* __restrict__ dyn,
                      const float* __restrict__ cw, float* __restrict__ v) {
    int idx = blockIdx.x * 256 + threadIdx.x;      // over T * VD/4
    int t = idx / (VD/4);
    if (t >= T_LEN) return;
    int c = (idx - t * (VD/4)) * 4;
    float d[4];
    #pragma unroll
    for (int j = 0; j < 4; j++) d[j] = dyn[t*4 + j];
    float a0 = 0.f, a1 = 0.f, a2 = 0.f, a3 = 0.f;
    #pragma unroll
    for (int j = 0; j < 4; j++) {
        int tt = t + j - 3;
        if (tt >= 0) {
            float4 xv = *(const float4*)(x + (size_t)tt * VD + c);
            a0 += (cw[(c+0)*4 + j] + d[j]) * xv.x;
            a1 += (cw[(c+1)*4 + j] + d[j]) * xv.y;
            a2 += (cw[(c+2)*4 + j] + d[j]) * xv.z;
            a3 += (cw[(c+3)*4 + j] + d[j]) * xv.w;
        }
    }
    float4 r;
    r.x = siluf(a0); r.y = siluf(a1); r.z = siluf(a2); r.w = siluf(a3);
    *(float4*)(v + (size_t)t * VD + c) = r;
}

// ---------------- fused l2norm(q), l2norm(k), qk = q·k (warp per (t,h)) ----------------
__global__ __launch_bounds__(256)
void l2qk_kernel(float* __restrict__ q, float* __restrict__ k, float* __restrict__ qk) {
    int vec  = blockIdx.x * 8 + (threadIdx.x >> 5);   // t*6 + h
    int lane = threadIdx.x & 31;
    float* qr = q + (size_t)vec * DKDIM;
    float* kr = k + (size_t)vec * DKDIM;
    float xq[8], xk[8];
    float sq = 0.f, sk = 0.f, sx = 0.f;
    #pragma unroll
    for (int i = 0; i < 8; i++) {
        xq[i] = qr[lane + 32*i]; xk[i] = kr[lane + 32*i];
        sq += xq[i]*xq[i]; sk += xk[i]*xk[i]; sx += xq[i]*xk[i];
    }
    #pragma unroll
    for (int off = 16; off; off >>= 1) {
        sq += __shfl_xor_sync(0xffffffffu, sq, off);
        sk += __shfl_xor_sync(0xffffffffu, sk, off);
        sx += __shfl_xor_sync(0xffffffffu, sx, off);
    }
    float rq = rsqrtf(sq + 1e-6f) * 0.0625f;   // fold DK^-0.5 into q
    float rk = rsqrtf(sk + 1e-6f);
    #pragma unroll
    for (int i = 0; i < 8; i++) {
        qr[lane + 32*i] = xq[i] * rq;
        kr[lane + 32*i] = xk[i] * rk;
    }
    if (lane == 0) qk[vec] = sx * rq * rk;
}

// ---------------- gated delta-rule scan, one reduction phase per step ----------------
// Per warp: 2 state columns. Identity: q·S_new = q·S_dec + (q·k)·dv with qk precomputed.
// No SMEM, no __syncthreads; register double-buffered prefetch.
__global__ __launch_bounds__(128)
void scan_kernel(const float* __restrict__ q, const float* __restrict__ k,
                 const float* __restrict__ v, const float* __restrict__ eg,
                 const float* __restrict__ beta, const float* __restrict__ qk,
                 float* __restrict__ o) {
    const int warpg = blockIdx.x * 4 + (threadIdx.x >> 5);  // 0..1535
    const int c0    = warpg * 2;                            // flat v-column base
    const int head  = c0 >> 9;
    const int lane  = threadIdx.x & 31;

    const float* qb = q + head * DKDIM + lane;
    const float* kb = k + head * DKDIM + lane;

    float s0[8], s1[8];
    #pragma unroll
    for (int i = 0; i < 8; i++) { s0[i] = 0.f; s1[i] = 0.f; }

    float qA[8], kA[8], vA0, vA1, ebA, btA, qkA;
    float qB[8], kB[8], vB0, vB1, ebB, btB, qkB;

    #define SCAN_LOAD(t, qr, kr, v0, v1, eb, bt, qv) do {              \
        size_t _off = (size_t)(t) * KD;                                \
        _Pragma("unroll")                                              \
        for (int _i = 0; _i < 8; _i++) {                               \
            qr[_i] = qb[_off + 32*_i];                                 \
            kr[_i] = kb[_off + 32*_i];                                 \
        }                                                              \
        size_t _vo = (size_t)(t) * VD + c0;                            \
        v0 = v[_vo]; v1 = v[_vo + 1];                                  \
        eb = eg[(t)*6 + head]; bt = beta[(t)*6 + head];                \
        qv = qk[(t)*6 + head];                                         \
    } while (0)

    #define SCAN_STEP(t, qr, kr, v0, v1, eb, bt, qv) do {              \
        float d0 = 0.f, d1 = 0.f, p0 = 0.f, p1 = 0.f;                  \
        _Pragma("unroll")                                              \
        for (int _i = 0; _i < 8; _i++) {                               \
            float t0 = s0[_i] * eb, t1 = s1[_i] * eb;                  \
            s0[_i] = t0; s1[_i] = t1;                                  \
            d0 += kr[_i] * t0; d1 += kr[_i] * t1;                      \
            p0 += qr[_i] * t0; p1 += qr[_i] * t1;                      \
        }                                                              \
        _Pragma("unroll")                                              \
        for (int _off = 16; _off; _off >>= 1) {                        \
            d0 += __shfl_xor_sync(0xffffffffu, d0, _off);              \
            d1 += __shfl_xor_sync(0xffffffffu, d1, _off);              \
            p0 += __shfl_xor_sync(0xffffffffu, p0, _off);              \
            p1 += __shfl_xor_sync(0xffffffffu, p1, _off);              \
        }                                                              \
        float dv0 = (v0 - d0) * bt, dv1 = (v1 - d1) * bt;              \
        _Pragma("unroll")                                              \
        for (int _i = 0; _i < 8; _i++) {                               \
            s0[_i] += kr[_i] * dv0; s1[_i] += kr[_i] * dv1;            \
        }                                                              \
        if (lane == 0) {                                               \
            o[(size_t)(t) * VD + c0]     = p0 + qv * dv0;              \
            o[(size_t)(t) * VD + c0 + 1] = p1 + qv * dv1;              \
        }                                                              \
    } while (0)

    SCAN_LOAD(0, qA, kA, vA0, vA1, ebA, btA, qkA);
    for (int t = 0; t < T_LEN; t += 2) {
        SCAN_LOAD(t + 1, qB, kB, vB0, vB1, ebB, btB, qkB);
        SCAN_STEP(t, qA, kA, vA0, vA1, ebA, btA, qkA);
        if (t + 2 < T_LEN) SCAN_LOAD(t + 2, qA, kA, vA0, vA1, ebA, btA, qkA);
        SCAN_STEP(t + 1, qB, kB, vB0, vB1, ebB, btB, qkB);
    }
    #undef SCAN_LOAD
    #undef SCAN_STEP
}

// ---------------- gated RMSNorm -> tf32-rounded y ----------------
__global__ __launch_bounds__(128)
void rmsnorm_gate_kernel(const float* __restrict__ o, const float* __restrict__ gate,
                         const float* __restrict__ nw, float* __restrict__ y) {
    int row = blockIdx.x;                  // t*6 + h
    int tid = threadIdx.x;
    size_t base = (size_t)(row / 6) * VD + (size_t)(row % 6) * DVDIM;
    float4 ov = *(const float4*)(o + base + tid*4);
    float ss = ov.x*ov.x + ov.y*ov.y + ov.z*ov.z + ov.w*ov.w;
    #pragma unroll
    for (int off = 16; off; off >>= 1) ss += __shfl_xor_sync(0xffffffffu, ss, off);
    __shared__ float red[4];
    int w = tid >> 5, lane = tid & 31;
    if (lane == 0) red[w] = ss;
    __syncthreads();
    float tot = red[0] + red[1] + red[2] + red[3];
    float rms = rsqrtf(tot * (1.0f / (float)DVDIM) + 1e-5f);
    float4 gv = *(const float4*)(gate + base + tid*4);
    float4 nv = *(const float4*)(nw + tid*4);
    float4 r;
    r.x = f2tf32f(ov.x * rms * nv.x * siluf(gv.x));
    r.y = f2tf32f(ov.y * rms * nv.y * siluf(gv.y));
    r.z = f2tf32f(ov.z * rms * nv.z * siluf(gv.z));
    r.w = f2tf32f(ov.w * rms * nv.w * siluf(gv.w));
    *(float4*)(y + base + tid*4) = r;
}

// ---------------- launch ----------------
extern "C" void kernel_launch(void* const* d_in, const int* in_sizes, int n_in,
                              void* d_out, int out_size) {
    const float* h       = (const float*)d_in[0];
    const float* Wq      = (const float*)d_in[1];
    const float* Wk      = (const float*)d_in[2];
    const float* Wv      = (const float*)d_in[3];
    const float* Wb      = (const float*)d_in[4];
    const float* Wa      = (const float*)d_in[5];
    const float* Wg      = (const float*)d_in[6];
    const float* Wo      = (const float*)d_in[7];
    const float* A_log   = (const float*)d_in[8];
    const float* dt_bias = (const float*)d_in[9];
    const float* conv_w  = (const float*)d_in[10];
    const float* gen_w1  = (const float*)d_in[11];
    const float* gen_w2  = (const float*)d_in[12];
    const float* norm_w  = (const float*)d_in[13];
    float* out = (float*)d_out;

    float *pq, *pk, *px, *pv, *pd1, *pd, *peg, *pbeta, *pgate, *po, *pqk;
    float *phr, *pwqr, *pwkr, *pwvr, *pwgr, *pg1r, *pwor;
    cudaGetSymbolAddress((void**)&pq,    g_q);
    cudaGetSymbolAddress((void**)&pk,    g_k);
    cudaGetSymbolAddress((void**)&px,    g_x);
    cudaGetSymbolAddress((void**)&pv,    g_v);
    cudaGetSymbolAddress((void**)&pd1,   g_dyn1);
    cudaGetSymbolAddress((void**)&pd,    g_dyn);
    cudaGetSymbolAddress((void**)&peg,   g_eg);
    cudaGetSymbolAddress((void**)&pbeta, g_beta);
    cudaGetSymbolAddress((void**)&pgate, g_gate);
    cudaGetSymbolAddress((void**)&po,    g_o);
    cudaGetSymbolAddress((void**)&pqk,   g_qk);
    cudaGetSymbolAddress((void**)&phr,   g_hr);
    cudaGetSymbolAddress((void**)&pwqr,  g_wqr);
    cudaGetSymbolAddress((void**)&pwkr,  g_wkr);
    cudaGetSymbolAddress((void**)&pwvr,  g_wvr);
    cudaGetSymbolAddress((void**)&pwgr,  g_wgr);
    cudaGetSymbolAddress((void**)&pg1r,  g_g1r);
    cudaGetSymbolAddress((void**)&pwor,  g_wor);

    // tf32 pre-rounding of all GEMM operands
    auto rnd = [&](const float* s, float* d, size_t n) {
        int n4 = (int)(n / 4);
        round_kernel<<<(n4 + 255) / 256, 256>>>(s, d, n4);
    };
    rnd(h,      phr,  (size_t)T_LEN * D_DIM);
    rnd(Wq,     pwqr, (size_t)D_DIM * KD);
    rnd(Wk,     pwkr, (size_t)D_DIM * KD);
    rnd(Wv,     pwvr, (size_t)D_DIM * VD);
    rnd(Wg,     pwgr, (size_t)D_DIM * VD);
    rnd(gen_w1, pg1r, (size_t)D_DIM * GENW);
    rnd(Wo,     pwor, (size_t)VD * D_DIM);

    // fused projections: q|k|x|gate|dyn1 in one launch (74 x 32 tiles)
    proj_gemm_kernel<<<dim3(74, T_LEN/128), 256>>>(phr, pwqr, pwkr, pwvr, pwgr, pg1r,
                                                   pq, pk, px, pgate, pd1);

    dyn2_kernel<<<T_LEN/8, 256>>>(pd1, gen_w2, pd);
    betag_kernel<<<T_LEN, 256>>>(h, Wb, Wa, A_log, dt_bias, pbeta, peg);
    conv_silu_kernel<<<(T_LEN*(VD/4))/256, 256>>>(px, pd, conv_w, pv);

    l2qk_kernel<<<(T_LEN*H_N)/8, 256>>>(pq, pk, pqk);

    scan_kernel<<<VD/8, 128>>>(pq, pk, pv, peg, pbeta, pqk, po);

    rmsnorm_gate_kernel<<<T_LEN*H_N, 128>>>(po, pgate, norm_w, px);  // y (tf32) into g_x

    wo_gemm_kernel<<<dim3(D_DIM/128, T_LEN/128), 256>>>(px, pwor, out);
}

// round 4
// speedup vs baseline: 2.6700x; 1.0118x over previous
#include <cuda_runtime.h>
#include <cstdint>

// ---------------- problem constants ----------------
#define T_LEN 4096
#define D_DIM 2048
#define H_N   6
#define DKDIM 256
#define DVDIM 512
#define KD    1536   // H_N*DKDIM
#define VD    3072   // H_N*DVDIM
#define GENW  256
#define KSZ   4

// ---------------- scratch (static device, allocation-free) ----------------
__device__ float g_q[(size_t)T_LEN*KD];
__device__ float g_k[(size_t)T_LEN*KD];
__device__ float g_x[(size_t)T_LEN*VD];      // x = h@Wv; later reused as y (tf32-rounded)
__device__ float g_v[(size_t)T_LEN*VD];      // conv+silu output
__device__ float g_dyn1[(size_t)T_LEN*GENW];
__device__ float g_dyn[(size_t)T_LEN*4];
__device__ float g_eg[(size_t)T_LEN*H_N];    // exp(g)
__device__ float g_beta[(size_t)T_LEN*H_N];
__device__ float g_gate[(size_t)T_LEN*VD];
__device__ float g_o[(size_t)T_LEN*VD];      // scan output
__device__ float g_qk[(size_t)T_LEN*H_N];    // q·k per (t,head), post-norm

// tf32-pre-rounded copies (GEMM operands)
__device__ float g_hr [(size_t)T_LEN*D_DIM];
__device__ float g_wqr[(size_t)D_DIM*KD];
__device__ float g_wkr[(size_t)D_DIM*KD];
__device__ float g_wvr[(size_t)D_DIM*VD];
__device__ float g_wgr[(size_t)D_DIM*VD];
__device__ float g_g1r[(size_t)D_DIM*GENW];
__device__ float g_wor[(size_t)VD*D_DIM];

__device__ __forceinline__ float siluf(float x) { return x / (1.0f + expf(-x)); }

__device__ __forceinline__ float f2tf32f(float x) {
    uint32_t u;
    asm("cvt.rna.tf32.f32 %0, %1;" : "=r"(u) : "f"(x));
    return __uint_as_float(u);
}

// ---------------- fused tf32 pre-round copy: 7 segments, one launch ----------------
#define N4_H  2097152
#define N4_WQ 786432
#define N4_WK 786432
#define N4_WV 1572864
#define N4_WG 1572864
#define N4_G1 131072
#define N4_WO 1572864
#define N4_TOT (N4_H+N4_WQ+N4_WK+N4_WV+N4_WG+N4_G1+N4_WO)   // 8519680

__global__ __launch_bounds__(256)
void round_all_kernel(const float* __restrict__ h,  float* __restrict__ hr,
                      const float* __restrict__ wq, float* __restrict__ wqr,
                      const float* __restrict__ wk, float* __restrict__ wkr,
                      const float* __restrict__ wv, float* __restrict__ wvr,
                      const float* __restrict__ wg, float* __restrict__ wgr,
                      const float* __restrict__ g1, float* __restrict__ g1r,
                      const float* __restrict__ wo, float* __restrict__ wor) {
    long i = (long)blockIdx.x * 256 + threadIdx.x;
    const float* s; float* d;
    if (i < N4_H)                         { s = h;  d = hr; }
    else if ((i -= N4_H)  < N4_WQ)        { s = wq; d = wqr; }
    else if ((i -= N4_WQ) < N4_WK)        { s = wk; d = wkr; }
    else if ((i -= N4_WK) < N4_WV)        { s = wv; d = wvr; }
    else if ((i -= N4_WV) < N4_WG)        { s = wg; d = wgr; }
    else if ((i -= N4_WG) < N4_G1)        { s = g1; d = g1r; }
    else if ((i -= N4_G1) < N4_WO)        { s = wo; d = wor; }
    else return;
    float4 v = ((const float4*)s)[i];
    v.x = f2tf32f(v.x); v.y = f2tf32f(v.y);
    v.z = f2tf32f(v.z); v.w = f2tf32f(v.w);
    ((float4*)d)[i] = v;
}

// ---------------- cp.async helpers ----------------
__device__ __forceinline__ void cp16(void* smem, const void* gmem) {
    uint32_t sa = (uint32_t)__cvta_generic_to_shared(smem);
    asm volatile("cp.async.cg.shared.global [%0], [%1], 16;" :: "r"(sa), "l"(gmem) : "memory");
}

// ---------------- tf32 tensor-core GEMM body ----------------
// C[M,N] tile = act(A[.,K] @ B[K,Nseg]), inputs pre-rounded to tf32.
// BM=BN=128, BK=16, 256 threads, 2-stage cp.async pipeline, 2 CTAs/SM.
__device__ __forceinline__ void gemm_body(
    const float* __restrict__ A, const float* __restrict__ B, float* __restrict__ C,
    int K, int Nseg, int row0, int col0, int act)
{
    __shared__ float As[2][128][20];   // [stage][m][k] pad->20 (conflict-free frags)
    __shared__ float Bs[2][16][136];   // [stage][k][n] pad->136

    const int tid  = threadIdx.x;
    const int warp = tid >> 5, lane = tid & 31;
    const int gid  = lane >> 2, tig  = lane & 3;
    const int wm   = warp >> 1, wn   = warp & 1;

    const int aRow = tid >> 1, aC = (tid & 1) * 8;
    const int bKr  = tid >> 4, bN = (tid & 15) * 8;

    const float* Ab = A + (size_t)(row0 + aRow) * K + aC;
    const float* Bb = B + (size_t)bKr * Nseg + col0 + bN;

    float acc[2][8][4];
    #pragma unroll
    for (int i = 0; i < 2; i++)
        #pragma unroll
        for (int j = 0; j < 8; j++)
            #pragma unroll
            for (int c = 0; c < 4; c++) acc[i][j][c] = 0.0f;

    auto issue = [&](int st, int k0) {
        cp16(&As[st][aRow][aC],     Ab + k0);
        cp16(&As[st][aRow][aC + 4], Ab + k0 + 4);
        cp16(&Bs[st][bKr][bN],      Bb + (size_t)k0 * Nseg);
        cp16(&Bs[st][bKr][bN + 4],  Bb + (size_t)k0 * Nseg + 4);
        asm volatile("cp.async.commit_group;" ::: "memory");
    };

    const int KT = K >> 4;
    issue(0, 0);
    for (int kt = 0; kt < KT; ++kt) {
        const int cur = kt & 1;
        asm volatile("cp.async.wait_group 0;" ::: "memory");
        __syncthreads();
        if (kt + 1 < KT) issue(cur ^ 1, (kt + 1) * 16);

        #pragma unroll
        for (int kk = 0; kk < 16; kk += 8) {
            uint32_t af[2][4];
            #pragma unroll
            for (int i = 0; i < 2; ++i) {
                int m = wm*32 + i*16 + gid;
                af[i][0] = __float_as_uint(As[cur][m    ][kk + tig]);
                af[i][1] = __float_as_uint(As[cur][m + 8][kk + tig]);
                af[i][2] = __float_as_uint(As[cur][m    ][kk + tig + 4]);
                af[i][3] = __float_as_uint(As[cur][m + 8][kk + tig + 4]);
            }
            uint32_t bf[8][2];
            #pragma unroll
            for (int j = 0; j < 8; ++j) {
                int n = wn*64 + j*8 + gid;
                bf[j][0] = __float_as_uint(Bs[cur][kk + tig    ][n]);
                bf[j][1] = __float_as_uint(Bs[cur][kk + tig + 4][n]);
            }
            #pragma unroll
            for (int i = 0; i < 2; ++i)
                #pragma unroll
                for (int j = 0; j < 8; ++j) {
                    asm volatile(
                        "mma.sync.aligned.m16n8k8.row.col.f32.tf32.tf32.f32 "
                        "{%0,%1,%2,%3}, {%4,%5,%6,%7}, {%8,%9}, {%0,%1,%2,%3};"
                        : "+f"(acc[i][j][0]), "+f"(acc[i][j][1]),
                          "+f"(acc[i][j][2]), "+f"(acc[i][j][3])
                        : "r"(af[i][0]), "r"(af[i][1]), "r"(af[i][2]), "r"(af[i][3]),
                          "r"(bf[j][0]), "r"(bf[j][1]));
                }
        }
    }

    #pragma unroll
    for (int i = 0; i < 2; ++i) {
        int row = row0 + wm*32 + i*16 + gid;
        #pragma unroll
        for (int j = 0; j < 8; ++j) {
            int col = col0 + wn*64 + j*8 + 2*tig;
            float v0 = acc[i][j][0], v1 = acc[i][j][1];
            float v2 = acc[i][j][2], v3 = acc[i][j][3];
            if (act) { v0 = siluf(v0); v1 = siluf(v1); v2 = siluf(v2); v3 = siluf(v3); }
            *(float2*)(C + (size_t)row * Nseg + col)       = make_float2(v0, v1);
            *(float2*)(C + (size_t)(row + 8) * Nseg + col) = make_float2(v2, v3);
        }
    }
}

// ---------------- fused projection GEMM: Wq|Wk|Wv|Wg|gen_w1 ----------------
__global__ __launch_bounds__(256, 2)
void proj_gemm_kernel(const float* __restrict__ hR,
                      const float* __restrict__ WqR, const float* __restrict__ WkR,
                      const float* __restrict__ WvR, const float* __restrict__ WgR,
                      const float* __restrict__ g1R,
                      float* __restrict__ q, float* __restrict__ k,
                      float* __restrict__ x, float* __restrict__ g,
                      float* __restrict__ d1) {
    const int nt = blockIdx.x;   // 0..73 tile column
    const float* B; float* C; int Nseg, col0, act;
    if (nt < 12)      { B = WqR; C = q;  Nseg = KD;   col0 = nt*128;        act = 1; }
    else if (nt < 24) { B = WkR; C = k;  Nseg = KD;   col0 = (nt-12)*128;   act = 1; }
    else if (nt < 48) { B = WvR; C = x;  Nseg = VD;   col0 = (nt-24)*128;   act = 0; }
    else if (nt < 72) { B = WgR; C = g;  Nseg = VD;   col0 = (nt-48)*128;   act = 0; }
    else              { B = g1R; C = d1; Nseg = GENW; col0 = (nt-72)*128;   act = 1; }
    gemm_body(hR, B, C, D_DIM, Nseg, blockIdx.y * 128, col0, act);
}

// ---------------- output GEMM: out = y @ Wo ----------------
__global__ __launch_bounds__(256, 2)
void wo_gemm_kernel(const float* __restrict__ yR, const float* __restrict__ WoR,
                    float* __restrict__ out) {
    gemm_body(yR, WoR, out, VD, D_DIM, blockIdx.y * 128, blockIdx.x * 128, 0);
}

// ---------------- dyn = dyn1[T,256] @ gen_w2[256,4] (warp per token) ----------------
__global__ __launch_bounds__(256)
void dyn2_kernel(const float* __restrict__ dyn1, const float* __restrict__ w2,
                 float* __restrict__ dyn) {
    int t    = blockIdx.x * 8 + (threadIdx.x >> 5);
    int lane = threadIdx.x & 31;
    const float* r = dyn1 + (size_t)t * GENW;
    float a0 = 0.f, a1 = 0.f, a2 = 0.f, a3 = 0.f;
    #pragma unroll
    for (int i = 0; i < 8; i++) {
        int d = lane + 32*i;
        float v = r[d];
        const float* w = w2 + d*4;
        a0 += v*w[0]; a1 += v*w[1]; a2 += v*w[2]; a3 += v*w[3];
    }
    #pragma unroll
    for (int off = 16; off; off >>= 1) {
        a0 += __shfl_xor_sync(0xffffffffu, a0, off);
        a1 += __shfl_xor_sync(0xffffffffu, a1, off);
        a2 += __shfl_xor_sync(0xffffffffu, a2, off);
        a3 += __shfl_xor_sync(0xffffffffu, a3, off);
    }
    if (lane == 0) {
        dyn[t*4+0] = a0; dyn[t*4+1] = a1; dyn[t*4+2] = a2; dyn[t*4+3] = a3;
    }
}

// ---------------- beta = sigmoid(h@Wb), eg = exp(-exp(A_log)*softplus(h@Wa+dt_bias)) ----------------
__global__ __launch_bounds__(256)
void betag_kernel(const float* __restrict__ h, const float* __restrict__ Wb,
                  const float* __restrict__ Wa, const float* __restrict__ A_log,
                  const float* __restrict__ dt_bias,
                  float* __restrict__ beta, float* __restrict__ eg) {
    int t = blockIdx.x;
    const float* hr = h + (size_t)t * D_DIM;
    float acc[12];
    #pragma unroll
    for (int j = 0; j < 12; j++) acc[j] = 0.f;
    for (int d = threadIdx.x; d < D_DIM; d += 256) {
        float hv = hr[d];
        const float* wb = Wb + d*6;
        const float* wa = Wa + d*6;
        #pragma unroll
        for (int j = 0; j < 6; j++) {
            acc[j]   += hv * wb[j];
            acc[6+j] += hv * wa[j];
        }
    }
    #pragma unroll
    for (int j = 0; j < 12; j++)
        #pragma unroll
        for (int off = 16; off; off >>= 1)
            acc[j] += __shfl_xor_sync(0xffffffffu, acc[j], off);

    __shared__ float red[8][12];
    int w = threadIdx.x >> 5, lane = threadIdx.x & 31;
    if (lane == 0) {
        #pragma unroll
        for (int j = 0; j < 12; j++) red[w][j] = acc[j];
    }
    __syncthreads();
    if (threadIdx.x < 12) {
        float s = 0.f;
        #pragma unroll
        for (int i = 0; i < 8; i++) s += red[i][threadIdx.x];
        int j = threadIdx.x;
        if (j < 6) {
            beta[t*6 + j] = 1.0f / (1.0f + expf(-s));
        } else {
            int hh = j - 6;
            float xx = s + dt_bias[hh];
            float sp = (xx > 20.0f) ? xx : log1pf(expf(xx));
            float g  = -expf(A_log[hh]) * sp;
            eg[t*6 + hh] = expf(g);
        }
    }
}

// ---------------- dynamic short conv + silu ----------------
__global__ __launch_bounds__(256)
void conv_silu_kernel(const float* __restrict__ x, const float* __restrict__ dyn,
                      const float* __restrict__ cw, float* __restrict__ v) {
    int idx = blockIdx.x * 256 + threadIdx.x;      // over T * VD/4
    int t = idx / (VD/4);
    if (t >= T_LEN) return;
    int c = (idx - t * (VD/4)) * 4;
    float d[4];
    #pragma unroll
    for (int j = 0; j < 4; j++) d[j] = dyn[t*4 + j];
    float a0 = 0.f, a1 = 0.f, a2 = 0.f, a3 = 0.f;
    #pragma unroll
    for (int j = 0; j < 4; j++) {
        int tt = t + j - 3;
        if (tt >= 0) {
            float4 xv = *(const float4*)(x + (size_t)tt * VD + c);
            a0 += (cw[(c+0)*4 + j] + d[j]) * xv.x;
            a1 += (cw[(c+1)*4 + j] + d[j]) * xv.y;
            a2 += (cw[(c+2)*4 + j] + d[j]) * xv.z;
            a3 += (cw[(c+3)*4 + j] + d[j]) * xv.w;
        }
    }
    float4 r;
    r.x = siluf(a0); r.y = siluf(a1); r.z = siluf(a2); r.w = siluf(a3);
    *(float4*)(v + (size_t)t * VD + c) = r;
}

// ---------------- fused l2norm(q), l2norm(k), qk = q·k (warp per (t,h)) ----------------
__global__ __launch_bounds__(256)
void l2qk_kernel(float* __restrict__ q, float* __restrict__ k, float* __restrict__ qk) {
    int vec  = blockIdx.x * 8 + (threadIdx.x >> 5);   // t*6 + h
    int lane = threadIdx.x & 31;
    float* qr = q + (size_t)vec * DKDIM;
    float* kr = k + (size_t)vec * DKDIM;
    float xq[8], xk[8];
    float sq = 0.f, sk = 0.f, sx = 0.f;
    #pragma unroll
    for (int i = 0; i < 8; i++) {
        xq[i] = qr[lane + 32*i]; xk[i] = kr[lane + 32*i];
        sq += xq[i]*xq[i]; sk += xk[i]*xk[i]; sx += xq[i]*xk[i];
    }
    #pragma unroll
    for (int off = 16; off; off >>= 1) {
        sq += __shfl_xor_sync(0xffffffffu, sq, off);
        sk += __shfl_xor_sync(0xffffffffu, sk, off);
        sx += __shfl_xor_sync(0xffffffffu, sx, off);
    }
    float rq = rsqrtf(sq + 1e-6f) * 0.0625f;   // fold DK^-0.5 into q
    float rk = rsqrtf(sk + 1e-6f);
    #pragma unroll
    for (int i = 0; i < 8; i++) {
        qr[lane + 32*i] = xq[i] * rq;
        kr[lane + 32*i] = xk[i] * rk;
    }
    if (lane == 0) qk[vec] = sx * rq * rk;
}

// ---------------- gated delta-rule scan, one reduction phase per step ----------------
__global__ __launch_bounds__(128)
void scan_kernel(const float* __restrict__ q, const float* __restrict__ k,
                 const float* __restrict__ v, const float* __restrict__ eg,
                 const float* __restrict__ beta, const float* __restrict__ qk,
                 float* __restrict__ o) {
    const int warpg = blockIdx.x * 4 + (threadIdx.x >> 5);  // 0..1535
    const int c0    = warpg * 2;                            // flat v-column base
    const int head  = c0 >> 9;
    const int lane  = threadIdx.x & 31;

    const float* qb = q + head * DKDIM + lane;
    const float* kb = k + head * DKDIM + lane;

    float s0[8], s1[8];
    #pragma unroll
    for (int i = 0; i < 8; i++) { s0[i] = 0.f; s1[i] = 0.f; }

    float qA[8], kA[8], vA0, vA1, ebA, btA, qkA;
    float qB[8], kB[8], vB0, vB1, ebB, btB, qkB;

    #define SCAN_LOAD(t, qr, kr, v0, v1, eb, bt, qv) do {              \
        size_t _off = (size_t)(t) * KD;                                \
        _Pragma("unroll")                                              \
        for (int _i = 0; _i < 8; _i++) {                               \
            qr[_i] = qb[_off + 32*_i];                                 \
            kr[_i] = kb[_off + 32*_i];                                 \
        }                                                              \
        size_t _vo = (size_t)(t) * VD + c0;                            \
        v0 = v[_vo]; v1 = v[_vo + 1];                                  \
        eb = eg[(t)*6 + head]; bt = beta[(t)*6 + head];                \
        qv = qk[(t)*6 + head];                                         \
    } while (0)

    #define SCAN_STEP(t, qr, kr, v0, v1, eb, bt, qv) do {              \
        float d0 = 0.f, d1 = 0.f, p0 = 0.f, p1 = 0.f;                  \
        _Pragma("unroll")                                              \
        for (int _i = 0; _i < 8; _i++) {                               \
            float t0 = s0[_i] * eb, t1 = s1[_i] * eb;                  \
            s0[_i] = t0; s1[_i] = t1;                                  \
            d0 += kr[_i] * t0; d1 += kr[_i] * t1;                      \
            p0 += qr[_i] * t0; p1 += qr[_i] * t1;                      \
        }                                                              \
        _Pragma("unroll")                                              \
        for (int _off = 16; _off; _off >>= 1) {                        \
            d0 += __shfl_xor_sync(0xffffffffu, d0, _off);              \
            d1 += __shfl_xor_sync(0xffffffffu, d1, _off);              \
            p0 += __shfl_xor_sync(0xffffffffu, p0, _off);              \
            p1 += __shfl_xor_sync(0xffffffffu, p1, _off);              \
        }                                                              \
        float dv0 = (v0 - d0) * bt, dv1 = (v1 - d1) * bt;              \
        _Pragma("unroll")                                              \
        for (int _i = 0; _i < 8; _i++) {                               \
            s0[_i] += kr[_i] * dv0; s1[_i] += kr[_i] * dv1;            \
        }                                                              \
        if (lane == 0) {                                               \
            o[(size_t)(t) * VD + c0]     = p0 + qv * dv0;              \
            o[(size_t)(t) * VD + c0 + 1] = p1 + qv * dv1;              \
        }                                                              \
    } while (0)

    SCAN_LOAD(0, qA, kA, vA0, vA1, ebA, btA, qkA);
    for (int t = 0; t < T_LEN; t += 2) {
        SCAN_LOAD(t + 1, qB, kB, vB0, vB1, ebB, btB, qkB);
        SCAN_STEP(t, qA, kA, vA0, vA1, ebA, btA, qkA);
        if (t + 2 < T_LEN) SCAN_LOAD(t + 2, qA, kA, vA0, vA1, ebA, btA, qkA);
        SCAN_STEP(t + 1, qB, kB, vB0, vB1, ebB, btB, qkB);
    }
    #undef SCAN_LOAD
    #undef SCAN_STEP
}

// ---------------- gated RMSNorm -> tf32-rounded y ----------------
__global__ __launch_bounds__(128)
void rmsnorm_gate_kernel(const float* __restrict__ o, const float* __restrict__ gate,
                         const float* __restrict__ nw, float* __restrict__ y) {
    int row = blockIdx.x;                  // t*6 + h
    int tid = threadIdx.x;
    size_t base = (size_t)(row / 6) * VD + (size_t)(row % 6) * DVDIM;
    float4 ov = *(const float4*)(o + base + tid*4);
    float ss = ov.x*ov.x + ov.y*ov.y + ov.z*ov.z + ov.w*ov.w;
    #pragma unroll
    for (int off = 16; off; off >>= 1) ss += __shfl_xor_sync(0xffffffffu, ss, off);
    __shared__ float red[4];
    int w = tid >> 5, lane = tid & 31;
    if (lane == 0) red[w] = ss;
    __syncthreads();
    float tot = red[0] + red[1] + red[2] + red[3];
    float rms = rsqrtf(tot * (1.0f / (float)DVDIM) + 1e-5f);
    float4 gv = *(const float4*)(gate + base + tid*4);
    float4 nv = *(const float4*)(nw + tid*4);
    float4 r;
    r.x = f2tf32f(ov.x * rms * nv.x * siluf(gv.x));
    r.y = f2tf32f(ov.y * rms * nv.y * siluf(gv.y));
    r.z = f2tf32f(ov.z * rms * nv.z * siluf(gv.z));
    r.w = f2tf32f(ov.w * rms * nv.w * siluf(gv.w));
    *(float4*)(y + base + tid*4) = r;
}

// ---------------- launch ----------------
extern "C" void kernel_launch(void* const* d_in, const int* in_sizes, int n_in,
                              void* d_out, int out_size) {
    const float* h       = (const float*)d_in[0];
    const float* Wq      = (const float*)d_in[1];
    const float* Wk      = (const float*)d_in[2];
    const float* Wv      = (const float*)d_in[3];
    const float* Wb      = (const float*)d_in[4];
    const float* Wa      = (const float*)d_in[5];
    const float* Wg      = (const float*)d_in[6];
    const float* Wo      = (const float*)d_in[7];
    const float* A_log   = (const float*)d_in[8];
    const float* dt_bias = (const float*)d_in[9];
    const float* conv_w  = (const float*)d_in[10];
    const float* gen_w1  = (const float*)d_in[11];
    const float* gen_w2  = (const float*)d_in[12];
    const float* norm_w  = (const float*)d_in[13];
    float* out = (float*)d_out;

    float *pq, *pk, *px, *pv, *pd1, *pd, *peg, *pbeta, *pgate, *po, *pqk;
    float *phr, *pwqr, *pwkr, *pwvr, *pwgr, *pg1r, *pwor;
    cudaGetSymbolAddress((void**)&pq,    g_q);
    cudaGetSymbolAddress((void**)&pk,    g_k);
    cudaGetSymbolAddress((void**)&px,    g_x);
    cudaGetSymbolAddress((void**)&pv,    g_v);
    cudaGetSymbolAddress((void**)&pd1,   g_dyn1);
    cudaGetSymbolAddress((void**)&pd,    g_dyn);
    cudaGetSymbolAddress((void**)&peg,   g_eg);
    cudaGetSymbolAddress((void**)&pbeta, g_beta);
    cudaGetSymbolAddress((void**)&pgate, g_gate);
    cudaGetSymbolAddress((void**)&po,    g_o);
    cudaGetSymbolAddress((void**)&pqk,   g_qk);
    cudaGetSymbolAddress((void**)&phr,   g_hr);
    cudaGetSymbolAddress((void**)&pwqr,  g_wqr);
    cudaGetSymbolAddress((void**)&pwkr,  g_wkr);
    cudaGetSymbolAddress((void**)&pwvr,  g_wvr);
    cudaGetSymbolAddress((void**)&pwgr,  g_wgr);
    cudaGetSymbolAddress((void**)&pg1r,  g_g1r);
    cudaGetSymbolAddress((void**)&pwor,  g_wor);

    // tf32 pre-rounding of all GEMM operands in ONE launch
    round_all_kernel<<<(N4_TOT + 255) / 256, 256>>>(h, phr, Wq, pwqr, Wk, pwkr,
                                                    Wv, pwvr, Wg, pwgr,
                                                    gen_w1, pg1r, Wo, pwor);

    // fused projections: q|k|x|gate|dyn1 in one launch (74 x 32 tiles)
    proj_gemm_kernel<<<dim3(74, T_LEN/128), 256>>>(phr, pwqr, pwkr, pwvr, pwgr, pg1r,
                                                   pq, pk, px, pgate, pd1);

    dyn2_kernel<<<T_LEN/8, 256>>>(pd1, gen_w2, pd);
    betag_kernel<<<T_LEN, 256>>>(h, Wb, Wa, A_log, dt_bias, pbeta, peg);
    conv_silu_kernel<<<(T_LEN*(VD/4))/256, 256>>>(px, pd, conv_w, pv);

    l2qk_kernel<<<(T_LEN*H_N)/8, 256>>>(pq, pk, pqk);

    scan_kernel<<<VD/8, 128>>>(pq, pk, pv, peg, pbeta, pqk, po);

    rmsnorm_gate_kernel<<<T_LEN*H_N, 128>>>(po, pgate, norm_w, px);  // y (tf32) into g_x

    wo_gemm_kernel<<<dim3(D_DIM/128, T_LEN/128), 256>>>(px, pwor, out);
}

// round 6
// speedup vs baseline: 2.8142x; 1.0540x over previous
#include <cuda_runtime.h>
#include <cstdint>

// ---------------- problem constants ----------------
#define T_LEN 4096
#define D_DIM 2048
#define H_N   6
#define DKDIM 256
#define DVDIM 512
#define KD    1536   // H_N*DKDIM
#define VD    3072   // H_N*DVDIM
#define GENW  256
#define KSZ   4

// ---------------- scratch (static device, allocation-free) ----------------
__device__ float g_q[(size_t)T_LEN*KD];
__device__ float g_k[(size_t)T_LEN*KD];
__device__ float g_x[(size_t)T_LEN*VD];      // x = h@Wv; later reused as y (permuted tf32)
__device__ float g_v[(size_t)T_LEN*VD];      // conv+silu output
__device__ float g_dyn1[(size_t)T_LEN*GENW];
__device__ float g_eg[(size_t)T_LEN*H_N];    // exp(g)
__device__ float g_beta[(size_t)T_LEN*H_N];
__device__ float g_gate[(size_t)T_LEN*VD];
__device__ float g_o[(size_t)T_LEN*VD];      // scan output
__device__ float g_qk[(size_t)T_LEN*H_N];    // q·k per (t,head), post-norm

// tf32-rounded, k-permuted GEMM operands (weights also transposed to [N,K])
__device__ float g_hr [(size_t)T_LEN*D_DIM];
__device__ float g_wqr[(size_t)KD*D_DIM];
__device__ float g_wkr[(size_t)KD*D_DIM];
__device__ float g_wvr[(size_t)VD*D_DIM];
__device__ float g_wgr[(size_t)VD*D_DIM];
__device__ float g_g1r[(size_t)GENW*D_DIM];
__device__ float g_wor[(size_t)D_DIM*VD];

__device__ __forceinline__ float siluf(float x) { return x / (1.0f + expf(-x)); }

__device__ __forceinline__ float f2tf32f(float x) {
    uint32_t u;
    asm("cvt.rna.tf32.f32 %0, %1;" : "=r"(u) : "f"(x));
    return __uint_as_float(u);
}
__device__ __forceinline__ uint32_t smem_u32(const void* p) {
    uint32_t a;
    asm("{ .reg .u64 t; cvta.to.shared.u64 t, %1; cvt.u32.u64 %0, t; }" : "=r"(a) : "l"(p));
    return a;
}
__device__ __forceinline__ void cp16s(uint32_t sa, const void* g) {
    asm volatile("cp.async.cg.shared.global [%0], [%1], 16;" :: "r"(sa), "l"(g) : "memory");
}

// ---------------- prep: tf32 round + k-permute (+ weight transpose) ----------------
// Layout: within each 16-wide k group, element k stored at pos (k%4)*4 + k/4,
// so an mma thread's {tig, tig+4, tig+8, tig+12} fragment = one 16B slot.
// Grid: first 2048 blocks handle h [T,D]; remaining 6272 transpose weights.
__global__ __launch_bounds__(256)
void prep_kernel(const float* __restrict__ h,
                 const float* __restrict__ wq, const float* __restrict__ wk,
                 const float* __restrict__ wv, const float* __restrict__ wg,
                 const float* __restrict__ g1, const float* __restrict__ wo,
                 float* __restrict__ hr,
                 float* __restrict__ wqr, float* __restrict__ wkr,
                 float* __restrict__ wvr, float* __restrict__ wgr,
                 float* __restrict__ g1r, float* __restrict__ wor) {
    int b = blockIdx.x;
    if (b < 2048) {          // h: round + permute, one 16-group per thread
        size_t e0 = ((size_t)b * 256 + threadIdx.x) * 16;
        float4 r0 = *(const float4*)(h + e0);
        float4 r1 = *(const float4*)(h + e0 + 4);
        float4 r2 = *(const float4*)(h + e0 + 8);
        float4 r3 = *(const float4*)(h + e0 + 12);
        float4 o0 = make_float4(f2tf32f(r0.x), f2tf32f(r1.x), f2tf32f(r2.x), f2tf32f(r3.x));
        float4 o1 = make_float4(f2tf32f(r0.y), f2tf32f(r1.y), f2tf32f(r2.y), f2tf32f(r3.y));
        float4 o2 = make_float4(f2tf32f(r0.z), f2tf32f(r1.z), f2tf32f(r2.z), f2tf32f(r3.z));
        float4 o3 = make_float4(f2tf32f(r0.w), f2tf32f(r1.w), f2tf32f(r2.w), f2tf32f(r3.w));
        *(float4*)(hr + e0)      = o0;
        *(float4*)(hr + e0 + 4)  = o1;
        *(float4*)(hr + e0 + 8)  = o2;
        *(float4*)(hr + e0 + 12) = o3;
        return;
    }
    b -= 2048;
    const float* W; float* O; int K, N;
    if (b < 768)                 { W = wq; O = wqr; K = D_DIM; N = KD; }
    else if ((b -= 768) < 768)   { W = wk; O = wkr; K = D_DIM; N = KD; }
    else if ((b -= 768) < 1536)  { W = wv; O = wvr; K = D_DIM; N = VD; }
    else if ((b -= 1536) < 1536) { W = wg; O = wgr; K = D_DIM; N = VD; }
    else if ((b -= 1536) < 128)  { W = g1; O = g1r; K = D_DIM; N = GENW; }
    else                         { b -= 128; W = wo; O = wor; K = VD; N = D_DIM; }
    int ntx = N >> 6;
    int tn = b % ntx, tk = b / ntx;
    int kb = tk * 64, nb = tn * 64;
    __shared__ float tile[64][65];
    int c = threadIdx.x & 63, r0i = threadIdx.x >> 6;
    #pragma unroll
    for (int i = 0; i < 16; i++) {
        int r = r0i + i * 4;
        tile[r][c] = W[(size_t)(kb + r) * N + nb + c];
    }
    __syncthreads();
    int nl = threadIdx.x >> 2, grp = threadIdx.x & 3;
    float* orow = O + (size_t)(nb + nl) * K + kb + grp * 16;
    #pragma unroll
    for (int a = 0; a < 4; a++) {
        float4 o;
        o.x = f2tf32f(tile[grp*16 + a     ][nl]);
        o.y = f2tf32f(tile[grp*16 + a + 4 ][nl]);
        o.z = f2tf32f(tile[grp*16 + a + 8 ][nl]);
        o.w = f2tf32f(tile[grp*16 + a + 12][nl]);
        *(float4*)(orow + a * 4) = o;
    }
}

// ---------------- tf32 GEMM body (permuted operands, LDS.128 frags) ----------------
// C[row0:+128, col0:+128] = act(A @ B^T). A [M,K] permuted-k; B [N,K] permuted-k.
// BK=16, 4-stage cp.async ring (64KB dyn smem), 256 threads, 2 CTAs/SM.
#define GEMM_SMEM 65536

__device__ __forceinline__ void gemm_body(
    const float* __restrict__ A, const float* __restrict__ B, float* __restrict__ C,
    int K, int Ns, int row0, int col0, int act)
{
    extern __shared__ float sm[];          // 4 stages x 4096 floats (A 2048 | B 2048)
    const int tid  = threadIdx.x;
    const int warp = tid >> 5, lane = tid & 31;
    const int gid  = lane >> 2, tig = lane & 3;
    const int wm   = warp >> 1, wn = warp & 1;
    const int KT   = K >> 4;
    const uint32_t smb = smem_u32(sm);

    float acc[2][8][4];
    #pragma unroll
    for (int i = 0; i < 2; i++)
        #pragma unroll
        for (int j = 0; j < 8; j++)
            #pragma unroll
            for (int cc = 0; cc < 4; cc++) acc[i][j][cc] = 0.0f;

    const int rA = tid >> 2,        cA = (tid & 3) * 4;          // A chunk (rows 0..63 / +64)
    const float* Abase = A + (size_t)(row0 + rA) * K + cA;
    const float* Bbase = B + (size_t)(col0 + rA) * K + cA;

    auto issue = [&](int kt) {
        if (kt < KT) {
            uint32_t so = smb + (uint32_t)(kt & 3) * 16384u + (uint32_t)(rA * 16 + cA) * 4u;
            int k0 = kt << 4;
            cp16s(so,                 Abase + k0);
            cp16s(so + 4096,          Abase + k0 + (size_t)64 * K);
            cp16s(so + 8192,          Bbase + k0);
            cp16s(so + 8192 + 4096,   Bbase + k0 + (size_t)64 * K);
        }
        asm volatile("cp.async.commit_group;" ::: "memory");
    };

    issue(0); issue(1); issue(2);
    for (int kt = 0; kt < KT; ++kt) {
        asm volatile("cp.async.wait_group 2;" ::: "memory");
        __syncthreads();
        issue(kt + 3);

        const float* As = sm + (kt & 3) * 4096;
        const float* Bs = As + 2048;

        float4 A0[2], A1[2];
        #pragma unroll
        for (int i = 0; i < 2; i++) {
            int m = wm * 32 + i * 16 + gid;
            A0[i] = *(const float4*)(As + m * 16 + tig * 4);
            A1[i] = *(const float4*)(As + (m + 8) * 16 + tig * 4);
        }
        #pragma unroll
        for (int jh = 0; jh < 2; jh++) {
            float4 Bv[4];
            #pragma unroll
            for (int j = 0; j < 4; j++) {
                int n = wn * 64 + (jh * 4 + j) * 8 + gid;
                Bv[j] = *(const float4*)(Bs + n * 16 + tig * 4);
            }
            #pragma unroll
            for (int i = 0; i < 2; i++)
                #pragma unroll
                for (int j = 0; j < 4; j++) {
                    float* ac = acc[i][jh * 4 + j];
                    asm volatile(
                        "mma.sync.aligned.m16n8k8.row.col.f32.tf32.tf32.f32 "
                        "{%0,%1,%2,%3}, {%4,%5,%6,%7}, {%8,%9}, {%0,%1,%2,%3};"
                        : "+f"(ac[0]), "+f"(ac[1]), "+f"(ac[2]), "+f"(ac[3])
                        : "r"(__float_as_uint(A0[i].x)), "r"(__float_as_uint(A1[i].x)),
                          "r"(__float_as_uint(A0[i].y)), "r"(__float_as_uint(A1[i].y)),
                          "r"(__float_as_uint(Bv[j].x)), "r"(__float_as_uint(Bv[j].y)));
                    asm volatile(
                        "mma.sync.aligned.m16n8k8.row.col.f32.tf32.tf32.f32 "
                        "{%0,%1,%2,%3}, {%4,%5,%6,%7}, {%8,%9}, {%0,%1,%2,%3};"
                        : "+f"(ac[0]), "+f"(ac[1]), "+f"(ac[2]), "+f"(ac[3])
                        : "r"(__float_as_uint(A0[i].z)), "r"(__float_as_uint(A1[i].z)),
                          "r"(__float_as_uint(A0[i].w)), "r"(__float_as_uint(A1[i].w)),
                          "r"(__float_as_uint(Bv[j].z)), "r"(__float_as_uint(Bv[j].w)));
                }
        }
    }

    #pragma unroll
    for (int i = 0; i < 2; ++i) {
        int row = row0 + wm * 32 + i * 16 + gid;
        #pragma unroll
        for (int j = 0; j < 8; ++j) {
            int col = col0 + wn * 64 + j * 8 + 2 * tig;
            float v0 = acc[i][j][0], v1 = acc[i][j][1];
            float v2 = acc[i][j][2], v3 = acc[i][j][3];
            if (act) { v0 = siluf(v0); v1 = siluf(v1); v2 = siluf(v2); v3 = siluf(v3); }
            *(float2*)(C + (size_t)row * Ns + col)       = make_float2(v0, v1);
            *(float2*)(C + (size_t)(row + 8) * Ns + col) = make_float2(v2, v3);
        }
    }
}

// fused projections: blockIdx.y selects among q|k|x|gate|dyn1 column tiles
__global__ __launch_bounds__(256, 2)
void proj_gemm_kernel(const float* __restrict__ hR,
                      const float* __restrict__ WqR, const float* __restrict__ WkR,
                      const float* __restrict__ WvR, const float* __restrict__ WgR,
                      const float* __restrict__ g1R,
                      float* __restrict__ q, float* __restrict__ k,
                      float* __restrict__ x, float* __restrict__ g,
                      float* __restrict__ d1) {
    const int by = blockIdx.y;
    const float* B; float* C; int Ns, col0, act;
    if (by < 12)      { B = WqR; C = q;  Ns = KD;   col0 = by * 128;        act = 1; }
    else if (by < 24) { B = WkR; C = k;  Ns = KD;   col0 = (by - 12) * 128; act = 1; }
    else if (by < 48) { B = WvR; C = x;  Ns = VD;   col0 = (by - 24) * 128; act = 0; }
    else if (by < 72) { B = WgR; C = g;  Ns = VD;   col0 = (by - 48) * 128; act = 0; }
    else              { B = g1R; C = d1; Ns = GENW; col0 = (by - 72) * 128; act = 1; }
    gemm_body(hR, B, C, D_DIM, Ns, blockIdx.x * 128, col0, act);
}

__global__ __launch_bounds__(256, 2)
void wo_gemm_kernel(const float* __restrict__ yR, const float* __restrict__ WoR,
                    float* __restrict__ out) {
    gemm_body(yR, WoR, out, VD, D_DIM, blockIdx.x * 128, blockIdx.y * 128, 0);
}

// ---------------- fused per-token post: l2qk + dyn + betag + conv ----------------
__global__ __launch_bounds__(256)
void fused_post_kernel(const float* __restrict__ h,
                       const float* __restrict__ Wb, const float* __restrict__ Wa,
                       const float* __restrict__ A_log, const float* __restrict__ dt_bias,
                       float* __restrict__ q, float* __restrict__ k, float* __restrict__ qk,
                       const float* __restrict__ dyn1, const float* __restrict__ w2,
                       const float* __restrict__ cw,
                       const float* __restrict__ x, float* __restrict__ v,
                       float* __restrict__ beta, float* __restrict__ eg) {
    const int t = blockIdx.x;
    const int tid = threadIdx.x, wid = tid >> 5, lane = tid & 31;
    __shared__ float sdyn[4];
    __shared__ float red[8][12];

    // step 1: warps 0-5 -> l2norm(q,k)+qk per head; warp 6 -> dyn row
    if (wid < 6) {
        int vec = t * 6 + wid;
        float* qr = q + (size_t)vec * DKDIM;
        float* kr = k + (size_t)vec * DKDIM;
        float xq[8], xk[8];
        float sq = 0.f, sk = 0.f, sx = 0.f;
        #pragma unroll
        for (int i = 0; i < 8; i++) {
            xq[i] = qr[lane + 32*i]; xk[i] = kr[lane + 32*i];
            sq += xq[i]*xq[i]; sk += xk[i]*xk[i]; sx += xq[i]*xk[i];
        }
        #pragma unroll
        for (int off = 16; off; off >>= 1) {
            sq += __shfl_xor_sync(0xffffffffu, sq, off);
            sk += __shfl_xor_sync(0xffffffffu, sk, off);
            sx += __shfl_xor_sync(0xffffffffu, sx, off);
        }
        float rq = rsqrtf(sq + 1e-6f) * 0.0625f;   // fold DK^-0.5 into q
        float rk = rsqrtf(sk + 1e-6f);
        #pragma unroll
        for (int i = 0; i < 8; i++) {
            qr[lane + 32*i] = xq[i] * rq;
            kr[lane + 32*i] = xk[i] * rk;
        }
        if (lane == 0) qk[vec] = sx * rq * rk;
    } else if (wid == 6) {
        const float* r = dyn1 + (size_t)t * GENW;
        float a0 = 0.f, a1 = 0.f, a2 = 0.f, a3 = 0.f;
        #pragma unroll
        for (int i = 0; i < 8; i++) {
            int d = lane + 32*i;
            float vv = r[d];
            const float* w = w2 + d*4;
            a0 += vv*w[0]; a1 += vv*w[1]; a2 += vv*w[2]; a3 += vv*w[3];
        }
        #pragma unroll
        for (int off = 16; off; off >>= 1) {
            a0 += __shfl_xor_sync(0xffffffffu, a0, off);
            a1 += __shfl_xor_sync(0xffffffffu, a1, off);
            a2 += __shfl_xor_sync(0xffffffffu, a2, off);
            a3 += __shfl_xor_sync(0xffffffffu, a3, off);
        }
        if (lane == 0) { sdyn[0]=a0; sdyn[1]=a1; sdyn[2]=a2; sdyn[3]=a3; }
    }
    __syncthreads();

    // step 2: betag (all threads)
    const float* hr = h + (size_t)t * D_DIM;
    float acc[12];
    #pragma unroll
    for (int j = 0; j < 12; j++) acc[j] = 0.f;
    for (int d = tid; d < D_DIM; d += 256) {
        float hv = hr[d];
        const float* wb = Wb + d*6;
        const float* wa = Wa + d*6;
        #pragma unroll
        for (int j = 0; j < 6; j++) {
            acc[j]   += hv * wb[j];
            acc[6+j] += hv * wa[j];
        }
    }
    #pragma unroll
    for (int j = 0; j < 12; j++)
        #pragma unroll
        for (int off = 16; off; off >>= 1)
            acc[j] += __shfl_xor_sync(0xffffffffu, acc[j], off);
    if (lane == 0) {
        #pragma unroll
        for (int j = 0; j < 12; j++) red[wid][j] = acc[j];
    }
    __syncthreads();
    if (tid < 12) {
        float s = 0.f;
        #pragma unroll
        for (int i = 0; i < 8; i++) s += red[i][tid];
        if (tid < 6) {
            beta[t*6 + tid] = 1.0f / (1.0f + expf(-s));
        } else {
            int hh = tid - 6;
            float xx = s + dt_bias[hh];
            float sp = (xx > 20.0f) ? xx : log1pf(expf(xx));
            eg[t*6 + hh] = expf(-expf(A_log[hh]) * sp);
        }
    }

    // step 3: conv + silu (sdyn ready via the syncthreads above)
    float dd[4];
    #pragma unroll
    for (int j = 0; j < 4; j++) dd[j] = sdyn[j];
    #pragma unroll
    for (int gi = 0; gi < 3; gi++) {
        int c = gi * 1024 + tid * 4;
        float a0 = 0.f, a1 = 0.f, a2 = 0.f, a3 = 0.f;
        #pragma unroll
        for (int j = 0; j < 4; j++) {
            int tt = t + j - 3;
            if (tt >= 0) {
                float4 xv = *(const float4*)(x + (size_t)tt * VD + c);
                a0 += (cw[(c+0)*4 + j] + dd[j]) * xv.x;
                a1 += (cw[(c+1)*4 + j] + dd[j]) * xv.y;
                a2 += (cw[(c+2)*4 + j] + dd[j]) * xv.z;
                a3 += (cw[(c+3)*4 + j] + dd[j]) * xv.w;
            }
        }
        float4 r;
        r.x = siluf(a0); r.y = siluf(a1); r.z = siluf(a2); r.w = siluf(a3);
        *(float4*)(v + (size_t)t * VD + c) = r;
    }
}

// ---------------- gated delta-rule scan ----------------
__global__ __launch_bounds__(128)
void scan_kernel(const float* __restrict__ q, const float* __restrict__ k,
                 const float* __restrict__ v, const float* __restrict__ eg,
                 const float* __restrict__ beta, const float* __restrict__ qk,
                 float* __restrict__ o) {
    const int warpg = blockIdx.x * 4 + (threadIdx.x >> 5);
    const int c0    = warpg * 2;
    const int head  = c0 >> 9;
    const int lane  = threadIdx.x & 31;

    const float* qb = q + head * DKDIM + lane;
    const float* kb = k + head * DKDIM + lane;

    float s0[8], s1[8];
    #pragma unroll
    for (int i = 0; i < 8; i++) { s0[i] = 0.f; s1[i] = 0.f; }

    float qA[8], kA[8], vA0, vA1, ebA, btA, qkA;
    float qB[8], kB[8], vB0, vB1, ebB, btB, qkB;

    #define SCAN_LOAD(t, qr, kr, v0, v1, eb, bt, qv) do {              \
        size_t _off = (size_t)(t) * KD;                                \
        _Pragma("unroll")                                              \
        for (int _i = 0; _i < 8; _i++) {                               \
            qr[_i] = qb[_off + 32*_i];                                 \
            kr[_i] = kb[_off + 32*_i];                                 \
        }                                                              \
        size_t _vo = (size_t)(t) * VD + c0;                            \
        v0 = v[_vo]; v1 = v[_vo + 1];                                  \
        eb = eg[(t)*6 + head]; bt = beta[(t)*6 + head];                \
        qv = qk[(t)*6 + head];                                         \
    } while (0)

    #define SCAN_STEP(t, qr, kr, v0, v1, eb, bt, qv) do {              \
        float d0 = 0.f, d1 = 0.f, p0 = 0.f, p1 = 0.f;                  \
        _Pragma("unroll")                                              \
        for (int _i = 0; _i < 8; _i++) {                               \
            float t0 = s0[_i] * eb, t1 = s1[_i] * eb;                  \
            s0[_i] = t0; s1[_i] = t1;                                  \
            d0 += kr[_i] * t0; d1 += kr[_i] * t1;                      \
            p0 += qr[_i] * t0; p1 += qr[_i] * t1;                      \
        }                                                              \
        _Pragma("unroll")                                              \
        for (int _off = 16; _off; _off >>= 1) {                        \
            d0 += __shfl_xor_sync(0xffffffffu, d0, _off);              \
            d1 += __shfl_xor_sync(0xffffffffu, d1, _off);              \
            p0 += __shfl_xor_sync(0xffffffffu, p0, _off);              \
            p1 += __shfl_xor_sync(0xffffffffu, p1, _off);              \
        }                                                              \
        float dv0 = (v0 - d0) * bt, dv1 = (v1 - d1) * bt;              \
        _Pragma("unroll")                                              \
        for (int _i = 0; _i < 8; _i++) {                               \
            s0[_i] += kr[_i] * dv0; s1[_i] += kr[_i] * dv1;            \
        }                                                              \
        if (lane == 0) {                                               \
            o[(size_t)(t) * VD + c0]     = p0 + qv * dv0;              \
            o[(size_t)(t) * VD + c0 + 1] = p1 + qv * dv1;              \
        }                                                              \
    } while (0)

    SCAN_LOAD(0, qA, kA, vA0, vA1, ebA, btA, qkA);
    for (int t = 0; t < T_LEN; t += 2) {
        SCAN_LOAD(t + 1, qB, kB, vB0, vB1, ebB, btB, qkB);
        SCAN_STEP(t, qA, kA, vA0, vA1, ebA, btA, qkA);
        if (t + 2 < T_LEN) SCAN_LOAD(t + 2, qA, kA, vA0, vA1, ebA, btA, qkA);
        SCAN_STEP(t + 1, qB, kB, vB0, vB1, ebB, btB, qkB);
    }
    #undef SCAN_LOAD
    #undef SCAN_STEP
}

// ---------------- gated RMSNorm -> tf32-rounded, k-permuted y ----------------
__global__ __launch_bounds__(128)
void rmsnorm_gate_kernel(const float* __restrict__ o, const float* __restrict__ gate,
                         const float* __restrict__ nw, float* __restrict__ y) {
    int row = blockIdx.x;                  // t*6 + h
    int tid = threadIdx.x;
    size_t base = (size_t)(row / 6) * VD + (size_t)(row % 6) * DVDIM;
    int g = tid >> 2, a = tid & 3;

    float ov[4], gv[4], nv[4];
    float ss = 0.f;
    #pragma unroll
    for (int i = 0; i < 4; i++) {
        int c = g * 16 + a + 4 * i;
        ov[i] = o[base + c];
        gv[i] = gate[base + c];
        nv[i] = nw[c];
        ss += ov[i] * ov[i];
    }
    #pragma unroll
    for (int off = 16; off; off >>= 1) ss += __shfl_xor_sync(0xffffffffu, ss, off);
    __shared__ float red[4];
    int w = tid >> 5, lane = tid & 31;
    if (lane == 0) red[w] = ss;
    __syncthreads();
    float tot = red[0] + red[1] + red[2] + red[3];
    float rms = rsqrtf(tot * (1.0f / (float)DVDIM) + 1e-5f);

    float4 r;
    r.x = f2tf32f(ov[0] * rms * nv[0] * siluf(gv[0]));
    r.y = f2tf32f(ov[1] * rms * nv[1] * siluf(gv[1]));
    r.z = f2tf32f(ov[2] * rms * nv[2] * siluf(gv[2]));
    r.w = f2tf32f(ov[3] * rms * nv[3] * siluf(gv[3]));
    *(float4*)(y + base + g * 16 + 4 * a) = r;   // k-permuted slot
}

// ---------------- launch ----------------
extern "C" void kernel_launch(void* const* d_in, const int* in_sizes, int n_in,
                              void* d_out, int out_size) {
    const float* h       = (const float*)d_in[0];
    const float* Wq      = (const float*)d_in[1];
    const float* Wk      = (const float*)d_in[2];
    const float* Wv      = (const float*)d_in[3];
    const float* Wb      = (const float*)d_in[4];
    const float* Wa      = (const float*)d_in[5];
    const float* Wg      = (const float*)d_in[6];
    const float* Wo      = (const float*)d_in[7];
    const float* A_log   = (const float*)d_in[8];
    const float* dt_bias = (const float*)d_in[9];
    const float* conv_w  = (const float*)d_in[10];
    const float* gen_w1  = (const float*)d_in[11];
    const float* gen_w2  = (const float*)d_in[12];
    const float* norm_w  = (const float*)d_in[13];
    float* out = (float*)d_out;

    float *pq, *pk, *px, *pv, *pd1, *peg, *pbeta, *pgate, *po, *pqk;
    float *phr, *pwqr, *pwkr, *pwvr, *pwgr, *pg1r, *pwor;
    cudaGetSymbolAddress((void**)&pq,    g_q);
    cudaGetSymbolAddress((void**)&pk,    g_k);
    cudaGetSymbolAddress((void**)&px,    g_x);
    cudaGetSymbolAddress((void**)&pv,    g_v);
    cudaGetSymbolAddress((void**)&pd1,   g_dyn1);
    cudaGetSymbolAddress((void**)&peg,   g_eg);
    cudaGetSymbolAddress((void**)&pbeta, g_beta);
    cudaGetSymbolAddress((void**)&pgate, g_gate);
    cudaGetSymbolAddress((void**)&po,    g_o);
    cudaGetSymbolAddress((void**)&pqk,   g_qk);
    cudaGetSymbolAddress((void**)&phr,   g_hr);
    cudaGetSymbolAddress((void**)&pwqr,  g_wqr);
    cudaGetSymbolAddress((void**)&pwkr,  g_wkr);
    cudaGetSymbolAddress((void**)&pwvr,  g_wvr);
    cudaGetSymbolAddress((void**)&pwgr,  g_wgr);
    cudaGetSymbolAddress((void**)&pg1r,  g_g1r);
    cudaGetSymbolAddress((void**)&pwor,  g_wor);

    cudaFuncSetAttribute(proj_gemm_kernel, cudaFuncAttributeMaxDynamicSharedMemorySize, GEMM_SMEM);
    cudaFuncSetAttribute(wo_gemm_kernel,   cudaFuncAttributeMaxDynamicSharedMemorySize, GEMM_SMEM);

    // (0) round + permute h, transpose + round + permute weights
    prep_kernel<<<8320, 256>>>(h, Wq, Wk, Wv, Wg, gen_w1, Wo,
                               phr, pwqr, pwkr, pwvr, pwgr, pg1r, pwor);

    // (1) fused projections
    proj_gemm_kernel<<<dim3(T_LEN/128, 74), 256, GEMM_SMEM>>>(
        phr, pwqr, pwkr, pwvr, pwgr, pg1r, pq, pk, px, pgate, pd1);

    // (2) fused per-token post-processing
    fused_post_kernel<<<T_LEN, 256>>>(h, Wb, Wa, A_log, dt_bias,
                                      pq, pk, pqk, pd1, gen_w2, conv_w,
                                      px, pv, pbeta, peg);

    // (3) the serial scan (ncu profiles launch index 3)
    scan_kernel<<<VD/8, 128>>>(pq, pk, pv, peg, pbeta, pqk, po);

    // (4) gated RMSNorm -> permuted tf32 y (reuses g_x)
    rmsnorm_gate_kernel<<<T_LEN*H_N, 128>>>(po, pgate, norm_w, px);

    // (5) out = y @ Wo
    wo_gemm_kernel<<<dim3(T_LEN/128, D_DIM/128), 256, GEMM_SMEM>>>(px, pwor, out);
}